// round 10
// baseline (speedup 1.0000x reference)
#include <cuda_runtime.h>
#include <cuda_bf16.h>

#define NG      512
#define NODES   200
#define EDGES   6400
#define HID     128

typedef __nv_bfloat16 bf16;

// ---- activation buffers (bf16 hi/lo pairs) --------------------------------
__device__ bf16 g_hgh[NG * HID],  g_hgl[NG * HID];
__device__ bf16 g_x1h[NG * 512],  g_x1l[NG * 512];
__device__ bf16 g_x2h[NG * 1024], g_x2l[NG * 1024];
__device__ bf16 g_x3h[NG * 1024], g_x3l[NG * 1024];
__device__ bf16 g_x4h[NG * 512],  g_x4l[NG * 512];

// ---- pre-converted transposed weights [N][K] bf16 hi/lo -------------------
__device__ bf16 g_wta_h[512 * 128],   g_wta_l[512 * 128];
__device__ bf16 g_wtb_h[1024 * 512],  g_wtb_l[1024 * 512];
__device__ bf16 g_wtc_h[1024 * 1024], g_wtc_l[1024 * 1024];
__device__ bf16 g_wtd_h[512 * 1024],  g_wtd_l[512 * 1024];

// ---- PWL tables + readiness flag ------------------------------------------
__device__ float g_csorted[128];
__device__ float g_alpha[129 * 128];
__device__ float g_beta[129 * 128];
__device__ unsigned g_pwl_flag = 0;   // reset by head_softmax each launch

// ---- asm helpers -----------------------------------------------------------
__device__ __forceinline__ void cp16(void* smem, const void* gmem) {
    unsigned sa = (unsigned)__cvta_generic_to_shared(smem);
    asm volatile("cp.async.cg.shared.global [%0], [%1], 16;\n" :: "r"(sa), "l"(gmem));
}
__device__ __forceinline__ void cp_commit() {
    asm volatile("cp.async.commit_group;\n");
}
template <int N>
__device__ __forceinline__ void cp_wait() {
    asm volatile("cp.async.wait_group %0;\n" :: "n"(N));
}
__device__ __forceinline__ void ldsm4(unsigned r[4], const void* p) {
    unsigned a = (unsigned)__cvta_generic_to_shared(p);
    asm volatile("ldmatrix.sync.aligned.m8n8.x4.shared.b16 {%0,%1,%2,%3}, [%4];\n"
                 : "=r"(r[0]), "=r"(r[1]), "=r"(r[2]), "=r"(r[3]) : "r"(a));
}
__device__ __forceinline__ void ldsm4t(unsigned r[4], const void* p) {
    unsigned a = (unsigned)__cvta_generic_to_shared(p);
    asm volatile("ldmatrix.sync.aligned.m8n8.x4.trans.shared.b16 {%0,%1,%2,%3}, [%4];\n"
                 : "=r"(r[0]), "=r"(r[1]), "=r"(r[2]), "=r"(r[3]) : "r"(a));
}
__device__ __forceinline__ void mma_bf16(float c[4], const unsigned a[4],
                                         unsigned b0, unsigned b1) {
    asm volatile(
        "mma.sync.aligned.m16n8k16.row.col.f32.bf16.bf16.f32 "
        "{%0,%1,%2,%3}, {%4,%5,%6,%7}, {%8,%9}, {%0,%1,%2,%3};\n"
        : "+f"(c[0]), "+f"(c[1]), "+f"(c[2]), "+f"(c[3])
        : "r"(a[0]), "r"(a[1]), "r"(a[2]), "r"(a[3]), "r"(b0), "r"(b1));
}

// ===========================================================================
// PWL table builder (bids 0..15, 8 segments each). tid<128 active.
// ===========================================================================
__device__ void pwl_block(int p, unsigned char* smraw,
    const float* __restrict__ W1, const float* __restrict__ b1,
    const float* __restrict__ W2)
{
    float* sW2 = (float*)smraw;            // 16384 floats
    float* sc  = sW2 + 16384;
    float* sw  = sc + 128;
    float* sb  = sw + 128;
    float* ssc = sb + 128;
    int*  sidx = (int*)(ssc + 128);
    const int tid = threadIdx.x;

    for (int i = tid; i < 4096; i += 512)
        ((float4*)sW2)[i] = ((const float4*)W2)[i];
    if (tid < 128) {
        float w = W1[tid], b = b1[tid];
        sw[tid] = w; sb[tid] = b;
        sc[tid] = (w != 0.0f) ? (-b / w) : __int_as_float(0x7f800000);
    }
    __syncthreads();
    if (tid < 128) {
        float c = sc[tid];
        int r = 0;
        for (int j = 0; j < 128; j++) {
            float cj = sc[j];
            if (cj < c || (cj == c && j < tid)) r++;
        }
        sidx[r] = tid;
        ssc[r]  = c;
    }
    __syncthreads();
    if (tid < 128) {
        if (p == 0) g_csorted[tid] = ssc[tid];
        const int j  = tid;
        const int s0 = p * 8;
        float alpha = 0.0f, beta = 0.0f;
        for (int r = 0; r < 128; r++) {
            int k = sidx[r];
            float w = sw[k], b = sb[k];
            float W2kj = sW2[k * 128 + j];
            if (w == 0.0f) { if (b > 0.0f) beta += b * W2kj; continue; }
            bool active = (w > 0.0f) ? (r < s0) : (r >= s0);
            if (active) { alpha = fmaf(w, W2kj, alpha); beta = fmaf(b, W2kj, beta); }
        }
        for (int s = s0; s < s0 + 8; s++) {
            g_alpha[s * 128 + j] = alpha;
            g_beta[s * 128 + j]  = beta;
            int k = sidx[s];
            float w = sw[k], b = sb[k];
            float W2kj = sW2[k * 128 + j];
            float f = (w > 0.0f) ? 1.0f : ((w < 0.0f) ? -1.0f : 0.0f);
            alpha = fmaf(f * w, W2kj, alpha);
            beta  = fmaf(f * b, W2kj, beta);
        }
        if (p == 15) {
            g_alpha[128 * 128 + j] = alpha;
            g_beta[128 * 128 + j]  = beta;
        }
    }
    __syncthreads();
    if (tid == 0) {
        __threadfence();
        atomicAdd(&g_pwl_flag, 1u);
    }
}

// ===========================================================================
// Weight-convert prologue: grid-stride over 2112 32x32 transpose tiles.
// ===========================================================================
__device__ void conv_block(int w, int stride, unsigned char* smraw,
    const float* __restrict__ Wa, const float* __restrict__ Wb,
    const float* __restrict__ Wc, const float* __restrict__ Wd)
{
    float (*tile)[33] = (float(*)[33])smraw;
    const int tid = threadIdx.x;
    const int c = tid & 31, r = tid >> 5;   // r: 0..15

    for (int t = w; t < 2112; t += stride) {
        const float* W; bf16 *Oh, *Ol; int K, N, tl, tn;
        if (t < 64)        { W = Wa; Oh = g_wta_h; Ol = g_wta_l; K = 128;  N = 512;  tl = t;        tn = 16; }
        else if (t < 576)  { W = Wb; Oh = g_wtb_h; Ol = g_wtb_l; K = 512;  N = 1024; tl = t - 64;   tn = 32; }
        else if (t < 1600) { W = Wc; Oh = g_wtc_h; Ol = g_wtc_l; K = 1024; N = 1024; tl = t - 576;  tn = 32; }
        else               { W = Wd; Oh = g_wtd_h; Ol = g_wtd_l; K = 1024; N = 512;  tl = t - 1600; tn = 16; }
        int nb = (tl % tn) * 32, kb = (tl / tn) * 32;
        #pragma unroll
        for (int j = 0; j < 2; j++)
            tile[r + j * 16][c] = W[(size_t)(kb + r + j * 16) * N + nb + c];
        __syncthreads();
        #pragma unroll
        for (int j = 0; j < 2; j++) {
            int n = nb + r + j * 16;
            float v = tile[c][r + j * 16];
            bf16 h = __float2bfloat16(v);
            Oh[(size_t)n * K + kb + c] = h;
            Ol[(size_t)n * K + kb + c] = __float2bfloat16(v - __bfloat162float(h));
        }
        __syncthreads();
    }
}

// ===========================================================================
// Per-graph GNN block (SpMM via legacy mma; reordered MMA rounds).
// SMEM = 216,544 B
// ===========================================================================
#define CS 216
#define TSN 136

__device__ void gnn_block(int g, unsigned char* smraw,
    const int* __restrict__ src, const int* __restrict__ dst,
    const float* __restrict__ b2,
    bf16* __restrict__ hgh, bf16* __restrict__ hgl)
{
    bf16*  C    = (bf16*)smraw;
    bf16*  th   = C + 224 * CS;
    bf16*  tl   = th + 208 * TSN;
    float* s_a  = (float*)(tl + 208 * TSN);
    float* s_ii = s_a + 224;
    float* s_io = s_ii + 224;
    float* s_s  = s_io + 224;
    float* pool = s_s + 224;                 // 256
    float* colp = pool + 256;                // 448
    unsigned char* seg = (unsigned char*)(colp + 448); // 224

    const int tid   = threadIdx.x;
    const int ebase = g * EDGES;
    const int nbase = g * NODES;

    __syncthreads();   // smem handoff from pwl/conv prologue

    // --- 1. zero C fully; zero t pad rows ---
    {
        uint4 z = {0, 0, 0, 0};
        uint4* C4 = (uint4*)C;
        for (int i = tid; i < 224 * CS * 2 / 16; i += 512) C4[i] = z;
        uint4* tp = (uint4*)(th + 200 * TSN);
        uint4* lp = (uint4*)(tl + 200 * TSN);
        for (int i = tid; i < 8 * TSN * 2 / 16; i += 512) { tp[i] = z; lp[i] = z; }
    }
    __syncthreads();

    // --- 2. count matrix via bf16x2 atomics ---
    {
        const bf16 one = __float2bfloat16(1.0f);
        const bf16 zer = __float2bfloat16(0.0f);
        __nv_bfloat162 v10 = __halves2bfloat162(one, zer);
        __nv_bfloat162 v01 = __halves2bfloat162(zer, one);
        __nv_bfloat162* C2 = (__nv_bfloat162*)C;
        for (int e = tid; e < EDGES; e += 512) {
            int sl = src[ebase + e] - nbase;
            int dl = dst[ebase + e] - nbase;
            atomicAdd(&C2[dl * (CS / 2) + (sl >> 1)], (sl & 1) ? v01 : v10);
        }
    }
    __syncthreads();

    // --- 3. row sums (2-way split) ---
    if (tid < 448) {
        int r = tid % 224, half = tid / 224;
        const __nv_bfloat162* row = (const __nv_bfloat162*)C + r * (CS / 2) + half * 54;
        float sum = 0.0f;
        for (int w = 0; w < 54; w++) {
            float2 f = __bfloat1622float2(row[w]);
            sum += f.x + f.y;
        }
        colp[tid] = sum;
    }
    __syncthreads();
    if (tid < 224) {
        float sum = colp[tid] + colp[224 + tid];
        s_a[tid]  = sum;
        s_ii[tid] = rsqrtf(fmaxf(sum, 1.0f));
    }
    __syncthreads();

    // --- 4. col sums (2-way split over rows) ---
    if (tid < 432) {
        int cc = tid % 216, half = tid / 216;
        float sum = 0.0f;
        for (int d = half * 100; d < half * 100 + 100; d++)
            sum += __bfloat162float(C[d * CS + cc]);
        colp[tid] = sum;
    }
    __syncthreads();
    if (tid < CS) {
        float sum = colp[tid] + colp[216 + tid];
        float io = rsqrtf(fmaxf(sum, 1.0f));
        s_io[tid] = io;
        s_s[tid]  = s_a[tid] * io;
    }
    __syncthreads();

    // --- wait for PWL tables ---
    if (tid == 0) {
        unsigned v;
        do {
            asm volatile("ld.global.acquire.gpu.u32 %0, [%1];"
                         : "=r"(v) : "l"(&g_pwl_flag));
            if (v < 16u) __nanosleep(64);
        } while (v < 16u);
    }
    __syncthreads();

    // --- 5. layer-1 matvec (2-way split) + segment search ---
    if (tid < 400) {
        int d = tid % 200, half = tid / 200;
        const __nv_bfloat162* row = (const __nv_bfloat162*)C + d * (CS / 2) + half * 54;
        const float2* ss2 = (const float2*)s_s + half * 54;
        float sum = 0.0f;
        for (int w = 0; w < 54; w++) {
            float2 f = __bfloat1622float2(row[w]);
            float2 s = ss2[w];
            sum = fmaf(f.x, s.x, fmaf(f.y, s.y, sum));
        }
        colp[tid] = sum;
    }
    __syncthreads();
    if (tid < NODES) {
        float a = (colp[tid] + colp[200 + tid]) * s_ii[tid];
        s_a[tid] = a;
        int lo = 0, hi = 128;
        while (lo < hi) {
            int m = (lo + hi) >> 1;
            if (g_csorted[m] < a) lo = m + 1; else hi = m;
        }
        seg[tid] = (unsigned char)lo;
    }
    __syncthreads();

    // --- 6. t hi/lo ---
    for (int idx = tid; idx < NODES * 32; idx += 512) {
        int i = idx >> 5, q = idx & 31;
        float a  = s_a[i];
        float io = s_io[i];
        int   s  = seg[i];
        float4 al = ((const float4*)(g_alpha + s * 128))[q];
        float4 be = ((const float4*)(g_beta  + s * 128))[q];
        float v0 = fmaf(al.x, a, be.x) * io;
        float v1 = fmaf(al.y, a, be.y) * io;
        float v2 = fmaf(al.z, a, be.z) * io;
        float v3 = fmaf(al.w, a, be.w) * io;
        bf16 h0 = __float2bfloat16(v0), h1 = __float2bfloat16(v1);
        bf16 h2 = __float2bfloat16(v2), h3 = __float2bfloat16(v3);
        __nv_bfloat162 hp0 = __halves2bfloat162(h0, h1);
        __nv_bfloat162 hp1 = __halves2bfloat162(h2, h3);
        __nv_bfloat162 lp0 = __halves2bfloat162(
            __float2bfloat16(v0 - __bfloat162float(h0)),
            __float2bfloat16(v1 - __bfloat162float(h1)));
        __nv_bfloat162 lp1 = __halves2bfloat162(
            __float2bfloat16(v2 - __bfloat162float(h2)),
            __float2bfloat16(v3 - __bfloat162float(h3)));
        __nv_bfloat162* dh = (__nv_bfloat162*)(th + i * TSN + q * 4);
        __nv_bfloat162* dl = (__nv_bfloat162*)(tl + i * TSN + q * 4);
        dh[0] = hp0; dh[1] = hp1;
        dl[0] = lp0; dl[1] = lp1;
    }
    __syncthreads();

    // --- 7. MMA: acc = C @ (th + tl), rounds reordered for ILP ---
    const int lane = tid & 31;
    const int wid  = tid >> 5;
    const int wm   = wid & 1;
    const int wn   = wid >> 1;

    float c[7][2][4];
    #pragma unroll
    for (int mi = 0; mi < 7; mi++)
        #pragma unroll
        for (int ni = 0; ni < 2; ni++)
            #pragma unroll
            for (int q = 0; q < 4; q++) c[mi][ni][q] = 0.0f;

    const int aRow = wm * 112 + (lane & 15);
    const int aCol = ((lane >> 4) & 1) * 8;
    const int bRow = (lane & 7) + ((lane >> 4) & 1) * 8;
    const int bCol = wn * 16 + ((lane >> 3) & 1) * 8;

    for (int kt = 0; kt < 13; kt++) {
        unsigned bh[4], bl[4], af[7][4];
        const int kr = kt * 16 + bRow;
        ldsm4t(bh, th + kr * TSN + bCol);
        ldsm4t(bl, tl + kr * TSN + bCol);
        #pragma unroll
        for (int mi = 0; mi < 7; mi++)
            ldsm4(af[mi], C + (aRow + mi * 16) * CS + kt * 16 + aCol);
        #pragma unroll
        for (int mi = 0; mi < 7; mi++) mma_bf16(c[mi][0], af[mi], bh[0], bh[2]);
        #pragma unroll
        for (int mi = 0; mi < 7; mi++) mma_bf16(c[mi][1], af[mi], bh[1], bh[3]);
        #pragma unroll
        for (int mi = 0; mi < 7; mi++) mma_bf16(c[mi][0], af[mi], bl[0], bl[2]);
        #pragma unroll
        for (int mi = 0; mi < 7; mi++) mma_bf16(c[mi][1], af[mi], bl[1], bl[3]);
    }

    // --- 8. epilogue: relu + fused pool ---
    {
        const int gg = lane >> 2;
        const int tg = lane & 3;
        float bx[2], by[2];
        #pragma unroll
        for (int ni = 0; ni < 2; ni++) {
            int col = wn * 16 + ni * 8 + tg * 2;
            float2 bv = *(const float2*)(b2 + col);
            bx[ni] = bv.x; by[ni] = bv.y;
        }
        float ps[2][2] = {{0, 0}, {0, 0}};
        #pragma unroll
        for (int mi = 0; mi < 7; mi++) {
            int r0 = wm * 112 + mi * 16 + gg;
            int r1 = r0 + 8;
            float ii0 = (r0 < NODES) ? s_ii[r0] : 0.0f;
            float ii1 = (r1 < NODES) ? s_ii[r1] : 0.0f;
            #pragma unroll
            for (int ni = 0; ni < 2; ni++) {
                if (r0 < NODES) {
                    ps[ni][0] += fmaxf(fmaf(c[mi][ni][0], ii0, bx[ni]), 0.0f);
                    ps[ni][1] += fmaxf(fmaf(c[mi][ni][1], ii0, by[ni]), 0.0f);
                }
                if (r1 < NODES) {
                    ps[ni][0] += fmaxf(fmaf(c[mi][ni][2], ii1, bx[ni]), 0.0f);
                    ps[ni][1] += fmaxf(fmaf(c[mi][ni][3], ii1, by[ni]), 0.0f);
                }
            }
        }
        #pragma unroll
        for (int off = 16; off >= 4; off >>= 1) {
            #pragma unroll
            for (int ni = 0; ni < 2; ni++) {
                ps[ni][0] += __shfl_down_sync(0xffffffffu, ps[ni][0], off);
                ps[ni][1] += __shfl_down_sync(0xffffffffu, ps[ni][1], off);
            }
        }
        if (lane < 4) {
            #pragma unroll
            for (int ni = 0; ni < 2; ni++) {
                int col = wn * 16 + ni * 8 + lane * 2;
                pool[wm * 128 + col]     = ps[ni][0];
                pool[wm * 128 + col + 1] = ps[ni][1];
            }
        }
    }
    __syncthreads();
    if (tid < HID) {
        float v = (pool[tid] + pool[128 + tid]) * (1.0f / 200.0f);
        bf16 h = __float2bfloat16(v);
        hgh[g * HID + tid] = h;
        hgl[g * HID + tid] = __float2bfloat16(v - __bfloat162float(h));
    }
}

// ===========================================================================
// Merged kernel: 512 CTAs x 512 threads. bid<16: pwl; bid>=16: conv prologue;
// all: gnn for graph bid.
// ===========================================================================
__global__ void __launch_bounds__(512, 1) prep_gnn(
    const int* __restrict__ src, const int* __restrict__ dst,
    const float* __restrict__ W1, const float* __restrict__ b1,
    const float* __restrict__ W2, const float* __restrict__ b2,
    const float* __restrict__ Wa, const float* __restrict__ Wb,
    const float* __restrict__ Wc, const float* __restrict__ Wd,
    bf16* __restrict__ hgh, bf16* __restrict__ hgl)
{
    extern __shared__ unsigned char smraw[];
    const int bid = blockIdx.x;
    if (bid < 16) pwl_block(bid, smraw, W1, b1, W2);
    else          conv_block(bid - 16, 496, smraw, Wa, Wb, Wc, Wd);
    gnn_block(bid, smraw, src, dst, b2, hgh, hgl);
}

// ---------------------------------------------------------------------------
// bf16 hi/lo tensor-core GEMM, M-tile templated (32 or 64), N-tile 64.
// MT=32 -> ~31 KB SMEM -> 2-4 CTAs/SM (latency hiding across CTAs).
// ---------------------------------------------------------------------------
#define TSB 40

template <int MT>
__global__ void __launch_bounds__(256) gemm_bf16(
    const bf16* __restrict__ Ah, const bf16* __restrict__ Al,
    const bf16* __restrict__ Bh, const bf16* __restrict__ Bl,
    const float* __restrict__ bias,
    bf16* __restrict__ Oh, bf16* __restrict__ Ol,
    int K, int Nc)
{
    constexpr int MI = MT / 32;           // m16 tiles per warp
    __shared__ bf16 sAh[2][MT * TSB], sAl[2][MT * TSB];
    __shared__ bf16 sBh[2][64 * TSB], sBl[2][64 * TSB];

    const int tid  = threadIdx.x;
    const int lane = tid & 31;
    const int wid  = tid >> 5;
    const int wm   = wid & 1;
    const int wn   = wid >> 1;
    const int row0 = blockIdx.y * MT, col0 = blockIdx.x * 64;

    const int th  = tid & 127;
    const int lr  = th >> 2;
    const int lc  = (th & 3) * 8;
    const bool pl = (tid < 128);

    const bf16* gA = (pl ? Ah : Al) + (size_t)(row0 + (lr % MT)) * K + lc;
    const bf16* gB = (pl ? Bh : Bl) + (size_t)(col0 + lr) * K + lc;
    bf16* dA0 = (pl ? sAh[0] : sAl[0]) + (lr % MT) * TSB + lc;
    bf16* dB0 = (pl ? sBh[0] : sBl[0]) + lr * TSB + lc;
    bf16* dA1 = (pl ? sAh[1] : sAl[1]) + (lr % MT) * TSB + lc;
    bf16* dB1 = (pl ? sBh[1] : sBl[1]) + lr * TSB + lc;

    float c[MI][2][4];
    #pragma unroll
    for (int mi = 0; mi < MI; mi++)
        #pragma unroll
        for (int ni = 0; ni < 2; ni++)
            #pragma unroll
            for (int q = 0; q < 4; q++) c[mi][ni][q] = 0.0f;

    cp16(dA0, gA);
    if (MT == 64) cp16(dA0 + 32 * TSB, gA + (size_t)32 * K);
    cp16(dB0, gB);  cp16(dB0 + 32 * TSB, gB + (size_t)32 * K);
    cp_commit();

    const int nkt = K >> 5;
    const int frow = lane & 15;
    const int fk   = (lane >> 4) * 8;
    int buf = 0;

    for (int kt = 0; kt < nkt; kt++) {
        if (kt + 1 < nkt) {
            const bf16* gA1 = gA + (size_t)(kt + 1) * 32;
            const bf16* gB1 = gB + (size_t)(kt + 1) * 32;
            bf16* dA = buf ? dA0 : dA1;
            bf16* dB = buf ? dB0 : dB1;
            cp16(dA, gA1);
            if (MT == 64) cp16(dA + 32 * TSB, gA1 + (size_t)32 * K);
            cp16(dB, gB1); cp16(dB + 32 * TSB, gB1 + (size_t)32 * K);
            cp_commit();
            cp_wait<1>();
        } else {
            cp_wait<0>();
        }
        __syncthreads();

        #pragma unroll
        for (int ks = 0; ks < 32; ks += 16) {
            unsigned ah[MI][4], al[MI][4], bh[4], bl[4];
            #pragma unroll
            for (int mi = 0; mi < MI; mi++) {
                int ro = (wm * (MT / 2) + mi * 16 + frow) * TSB + ks + fk;
                ldsm4(ah[mi], &sAh[buf][ro]);
                ldsm4(al[mi], &sAl[buf][ro]);
            }
            {
                int no = (wn * 16 + frow) * TSB + ks + fk;
                ldsm4(bh, &sBh[buf][no]);
                ldsm4(bl, &sBl[buf][no]);
            }
            #pragma unroll
            for (int mi = 0; mi < MI; mi++) {
                mma_bf16(c[mi][0], ah[mi], bh[0], bh[2]);
                mma_bf16(c[mi][1], ah[mi], bh[1], bh[3]);
            }
            #pragma unroll
            for (int mi = 0; mi < MI; mi++) {
                mma_bf16(c[mi][0], ah[mi], bl[0], bl[2]);
                mma_bf16(c[mi][1], ah[mi], bl[1], bl[3]);
            }
            #pragma unroll
            for (int mi = 0; mi < MI; mi++) {
                mma_bf16(c[mi][0], al[mi], bh[0], bh[2]);
                mma_bf16(c[mi][1], al[mi], bh[1], bh[3]);
            }
        }
        __syncthreads();
        buf ^= 1;
    }

    const int g  = lane >> 2;
    const int tg = lane & 3;
    #pragma unroll
    for (int mi = 0; mi < MI; mi++) {
        #pragma unroll
        for (int ni = 0; ni < 2; ni++) {
            int r  = row0 + wm * (MT / 2) + mi * 16 + g;
            int cc = col0 + wn * 16 + ni * 8 + tg * 2;
            float2 bv = *(const float2*)(bias + cc);
            #pragma unroll
            for (int half = 0; half < 2; half++) {
                int rr = r + half * 8;
                float vx = fmaxf(c[mi][ni][half * 2 + 0] + bv.x, 0.0f);
                float vy = fmaxf(c[mi][ni][half * 2 + 1] + bv.y, 0.0f);
                bf16 hx = __float2bfloat16(vx);
                bf16 hy = __float2bfloat16(vy);
                __nv_bfloat162 hp(hx, hy);
                __nv_bfloat162 lp(__float2bfloat16(vx - __bfloat162float(hx)),
                                  __float2bfloat16(vy - __bfloat162float(hy)));
                *(__nv_bfloat162*)(Oh + (size_t)rr * Nc + cc) = hp;
                *(__nv_bfloat162*)(Ol + (size_t)rr * Nc + cc) = lp;
            }
        }
    }
}

// ---------------------------------------------------------------------------
// Final layer + flag reset for the next replay.
// ---------------------------------------------------------------------------
__global__ void __launch_bounds__(256) head_softmax(
    const bf16* __restrict__ Ah, const bf16* __restrict__ Al,
    const float* __restrict__ We, const float* __restrict__ be,
    float* __restrict__ out)
{
    if (blockIdx.x == 0 && threadIdx.x == 0) g_pwl_flag = 0;

    __shared__ float Ws[512 * 10];
    const int tid = threadIdx.x;
    for (int i = tid; i < 512 * 10; i += 256) Ws[i] = We[i];
    __syncthreads();
    const int lane = tid & 31, w = tid >> 5;
    const int row = blockIdx.x * 8 + w;

    float acc[10];
    #pragma unroll
    for (int c = 0; c < 10; c++) acc[c] = 0.0f;
    for (int k = lane; k < 512; k += 32) {
        float a = __bfloat162float(Ah[row * 512 + k]) +
                  __bfloat162float(Al[row * 512 + k]);
        #pragma unroll
        for (int c = 0; c < 10; c++) acc[c] = fmaf(a, Ws[k * 10 + c], acc[c]);
    }
    #pragma unroll
    for (int c = 0; c < 10; c++) {
        #pragma unroll
        for (int o = 16; o > 0; o >>= 1)
            acc[c] += __shfl_xor_sync(0xffffffffu, acc[c], o);
    }
    if (lane == 0) {
        float v[10], mx = -1e30f;
        #pragma unroll
        for (int c = 0; c < 10; c++) { v[c] = acc[c] + be[c]; mx = fmaxf(mx, v[c]); }
        float s = 0.0f;
        #pragma unroll
        for (int c = 0; c < 10; c++) { v[c] = __expf(v[c] - mx); s += v[c]; }
        float inv = 1.0f / s;
        #pragma unroll
        for (int c = 0; c < 10; c++) out[row * 10 + c] = v[c] * inv;
    }
}

// ---------------------------------------------------------------------------
extern "C" void kernel_launch(void* const* d_in, const int* in_sizes, int n_in,
                              void* d_out, int out_size)
{
    const int*   src = (const int*)  d_in[0];
    const int*   dst = (const int*)  d_in[1];
    const float* W1  = (const float*)d_in[2];
    const float* b1  = (const float*)d_in[3];
    const float* W2  = (const float*)d_in[4];
    const float* b2  = (const float*)d_in[5];
    const float* Wa  = (const float*)d_in[6];
    const float* ba  = (const float*)d_in[7];
    const float* Wb  = (const float*)d_in[8];
    const float* bb  = (const float*)d_in[9];
    const float* Wc  = (const float*)d_in[10];
    const float* bc  = (const float*)d_in[11];
    const float* Wd  = (const float*)d_in[12];
    const float* bd  = (const float*)d_in[13];
    const float* We  = (const float*)d_in[14];
    const float* be  = (const float*)d_in[15];
    float* out = (float*)d_out;

    bf16 *hgh, *hgl, *x1h, *x1l, *x2h, *x2l, *x3h, *x3l, *x4h, *x4l;
    bf16 *wah, *wal, *wbh, *wbl, *wch, *wcl, *wdh, *wdl;
    cudaGetSymbolAddress((void**)&hgh, g_hgh); cudaGetSymbolAddress((void**)&hgl, g_hgl);
    cudaGetSymbolAddress((void**)&x1h, g_x1h); cudaGetSymbolAddress((void**)&x1l, g_x1l);
    cudaGetSymbolAddress((void**)&x2h, g_x2h); cudaGetSymbolAddress((void**)&x2l, g_x2l);
    cudaGetSymbolAddress((void**)&x3h, g_x3h); cudaGetSymbolAddress((void**)&x3l, g_x3l);
    cudaGetSymbolAddress((void**)&x4h, g_x4h); cudaGetSymbolAddress((void**)&x4l, g_x4l);
    cudaGetSymbolAddress((void**)&wah, g_wta_h); cudaGetSymbolAddress((void**)&wal, g_wta_l);
    cudaGetSymbolAddress((void**)&wbh, g_wtb_h); cudaGetSymbolAddress((void**)&wbl, g_wtb_l);
    cudaGetSymbolAddress((void**)&wch, g_wtc_h); cudaGetSymbolAddress((void**)&wcl, g_wtc_l);
    cudaGetSymbolAddress((void**)&wdh, g_wtd_h); cudaGetSymbolAddress((void**)&wdl, g_wtd_l);

    const int SMEM = 224 * CS * 2 + 2 * 208 * TSN * 2
                   + 4 * 224 * 4 + 256 * 4 + 448 * 4 + 224;
    cudaFuncSetAttribute(prep_gnn, cudaFuncAttributeMaxDynamicSharedMemorySize, SMEM);

    prep_gnn<<<512, 512, SMEM>>>(src, dst, W1, b1, W2, b2, Wa, Wb, Wc, Wd, hgh, hgl);

    gemm_bf16<32><<<dim3(512 / 64,  512 / 32), 256>>>(hgh, hgl, wah, wal, ba, x1h, x1l, 128,  512);
    gemm_bf16<32><<<dim3(1024 / 64, 512 / 32), 256>>>(x1h, x1l, wbh, wbl, bb, x2h, x2l, 512,  1024);
    gemm_bf16<32><<<dim3(1024 / 64, 512 / 32), 256>>>(x2h, x2l, wch, wcl, bc, x3h, x3l, 1024, 1024);
    gemm_bf16<32><<<dim3(512 / 64,  512 / 32), 256>>>(x3h, x3l, wdh, wdl, bd, x4h, x4l, 1024, 512);

    head_softmax<<<64, 256>>>(x4h, x4l, We, be, out);
}

// round 11
// speedup vs baseline: 1.0095x; 1.0095x over previous
#include <cuda_runtime.h>
#include <cuda_bf16.h>

#define NG      512
#define NODES   200
#define EDGES   6400
#define HID     128

typedef __nv_bfloat16 bf16;

// ---- activation buffers (bf16 hi/lo pairs) --------------------------------
__device__ bf16 g_hgh[NG * HID],  g_hgl[NG * HID];
__device__ bf16 g_x1h[NG * 512],  g_x1l[NG * 512];
__device__ bf16 g_x2h[NG * 1024], g_x2l[NG * 1024];
__device__ bf16 g_x3h[NG * 1024], g_x3l[NG * 1024];
__device__ bf16 g_x4h[NG * 512],  g_x4l[NG * 512];

// ---- pre-converted transposed weights [N][K] bf16 hi/lo -------------------
__device__ bf16 g_wta_h[512 * 128],   g_wta_l[512 * 128];
__device__ bf16 g_wtb_h[1024 * 512],  g_wtb_l[1024 * 512];
__device__ bf16 g_wtc_h[1024 * 1024], g_wtc_l[1024 * 1024];
__device__ bf16 g_wtd_h[512 * 1024],  g_wtd_l[512 * 1024];

// ---- PWL tables + cross-kernel state (reset by head_softmax each launch) --
__device__ float g_csorted[128];
__device__ float g_alpha[129 * 128];
__device__ float g_beta[129 * 128];
__device__ unsigned g_pwl_flag = 0;
__device__ unsigned g_gnn_ctr  = 0;

// ---- asm helpers -----------------------------------------------------------
__device__ __forceinline__ void cp16(void* smem, const void* gmem) {
    unsigned sa = (unsigned)__cvta_generic_to_shared(smem);
    asm volatile("cp.async.cg.shared.global [%0], [%1], 16;\n" :: "r"(sa), "l"(gmem));
}
__device__ __forceinline__ void cp_commit() {
    asm volatile("cp.async.commit_group;\n");
}
template <int N>
__device__ __forceinline__ void cp_wait() {
    asm volatile("cp.async.wait_group %0;\n" :: "n"(N));
}
__device__ __forceinline__ void ldsm4(unsigned r[4], const void* p) {
    unsigned a = (unsigned)__cvta_generic_to_shared(p);
    asm volatile("ldmatrix.sync.aligned.m8n8.x4.shared.b16 {%0,%1,%2,%3}, [%4];\n"
                 : "=r"(r[0]), "=r"(r[1]), "=r"(r[2]), "=r"(r[3]) : "r"(a));
}
__device__ __forceinline__ void ldsm4t(unsigned r[4], const void* p) {
    unsigned a = (unsigned)__cvta_generic_to_shared(p);
    asm volatile("ldmatrix.sync.aligned.m8n8.x4.trans.shared.b16 {%0,%1,%2,%3}, [%4];\n"
                 : "=r"(r[0]), "=r"(r[1]), "=r"(r[2]), "=r"(r[3]) : "r"(a));
}
__device__ __forceinline__ void mma_bf16(float c[4], const unsigned a[4],
                                         unsigned b0, unsigned b1) {
    asm volatile(
        "mma.sync.aligned.m16n8k16.row.col.f32.bf16.bf16.f32 "
        "{%0,%1,%2,%3}, {%4,%5,%6,%7}, {%8,%9}, {%0,%1,%2,%3};\n"
        : "+f"(c[0]), "+f"(c[1]), "+f"(c[2]), "+f"(c[3])
        : "r"(a[0]), "r"(a[1]), "r"(a[2]), "r"(a[3]), "r"(b0), "r"(b1));
}

// ===========================================================================
// PWL table builder (bids 0..15, 8 segments each). tid<128 active.
// ===========================================================================
__device__ void pwl_block(int p, unsigned char* smraw,
    const float* __restrict__ W1, const float* __restrict__ b1,
    const float* __restrict__ W2)
{
    float* sW2 = (float*)smraw;            // 16384 floats
    float* sc  = sW2 + 16384;
    float* sw  = sc + 128;
    float* sb  = sw + 128;
    float* ssc = sb + 128;
    int*  sidx = (int*)(ssc + 128);
    const int tid = threadIdx.x;

    for (int i = tid; i < 4096; i += 512)
        ((float4*)sW2)[i] = ((const float4*)W2)[i];
    if (tid < 128) {
        float w = W1[tid], b = b1[tid];
        sw[tid] = w; sb[tid] = b;
        sc[tid] = (w != 0.0f) ? (-b / w) : __int_as_float(0x7f800000);
    }
    __syncthreads();
    if (tid < 128) {
        float c = sc[tid];
        int r = 0;
        for (int j = 0; j < 128; j++) {
            float cj = sc[j];
            if (cj < c || (cj == c && j < tid)) r++;
        }
        sidx[r] = tid;
        ssc[r]  = c;
    }
    __syncthreads();
    if (tid < 128) {
        if (p == 0) g_csorted[tid] = ssc[tid];
        const int j  = tid;
        const int s0 = p * 8;
        float alpha = 0.0f, beta = 0.0f;
        for (int r = 0; r < 128; r++) {
            int k = sidx[r];
            float w = sw[k], b = sb[k];
            float W2kj = sW2[k * 128 + j];
            if (w == 0.0f) { if (b > 0.0f) beta += b * W2kj; continue; }
            bool active = (w > 0.0f) ? (r < s0) : (r >= s0);
            if (active) { alpha = fmaf(w, W2kj, alpha); beta = fmaf(b, W2kj, beta); }
        }
        for (int s = s0; s < s0 + 8; s++) {
            g_alpha[s * 128 + j] = alpha;
            g_beta[s * 128 + j]  = beta;
            int k = sidx[s];
            float w = sw[k], b = sb[k];
            float W2kj = sW2[k * 128 + j];
            float f = (w > 0.0f) ? 1.0f : ((w < 0.0f) ? -1.0f : 0.0f);
            alpha = fmaf(f * w, W2kj, alpha);
            beta  = fmaf(f * b, W2kj, beta);
        }
        if (p == 15) {
            g_alpha[128 * 128 + j] = alpha;
            g_beta[128 * 128 + j]  = beta;
        }
    }
    __syncthreads();
    if (tid == 0) {
        __threadfence();
        atomicAdd(&g_pwl_flag, 1u);
    }
}

// ===========================================================================
// Weight-convert prologue: grid-stride over 2112 32x32 transpose tiles.
// ===========================================================================
__device__ void conv_block(int w, int stride, unsigned char* smraw,
    const float* __restrict__ Wa, const float* __restrict__ Wb,
    const float* __restrict__ Wc, const float* __restrict__ Wd)
{
    float (*tile)[33] = (float(*)[33])smraw;
    const int tid = threadIdx.x;
    const int c = tid & 31, r = tid >> 5;   // r: 0..15

    for (int t = w; t < 2112; t += stride) {
        const float* W; bf16 *Oh, *Ol; int K, N, tl, tn;
        if (t < 64)        { W = Wa; Oh = g_wta_h; Ol = g_wta_l; K = 128;  N = 512;  tl = t;        tn = 16; }
        else if (t < 576)  { W = Wb; Oh = g_wtb_h; Ol = g_wtb_l; K = 512;  N = 1024; tl = t - 64;   tn = 32; }
        else if (t < 1600) { W = Wc; Oh = g_wtc_h; Ol = g_wtc_l; K = 1024; N = 1024; tl = t - 576;  tn = 32; }
        else               { W = Wd; Oh = g_wtd_h; Ol = g_wtd_l; K = 1024; N = 512;  tl = t - 1600; tn = 16; }
        int nb = (tl % tn) * 32, kb = (tl / tn) * 32;
        #pragma unroll
        for (int j = 0; j < 2; j++)
            tile[r + j * 16][c] = W[(size_t)(kb + r + j * 16) * N + nb + c];
        __syncthreads();
        #pragma unroll
        for (int j = 0; j < 2; j++) {
            int n = nb + r + j * 16;
            float v = tile[c][r + j * 16];
            bf16 h = __float2bfloat16(v);
            Oh[(size_t)n * K + kb + c] = h;
            Ol[(size_t)n * K + kb + c] = __float2bfloat16(v - __bfloat162float(h));
        }
        __syncthreads();
    }
}

// ===========================================================================
// Per-graph GNN block (dense count-matrix + tensor-core SpMM).
// SMEM = 216,544 B
// ===========================================================================
#define CS 216
#define TSN 136

__device__ void gnn_block(int g, unsigned char* smraw,
    const int* __restrict__ src, const int* __restrict__ dst,
    const float* __restrict__ b2,
    bf16* __restrict__ hgh, bf16* __restrict__ hgl)
{
    bf16*  C    = (bf16*)smraw;
    bf16*  th   = C + 224 * CS;
    bf16*  tl   = th + 208 * TSN;
    float* s_a  = (float*)(tl + 208 * TSN);
    float* s_ii = s_a + 224;
    float* s_io = s_ii + 224;
    float* s_s  = s_io + 224;
    float* pool = s_s + 224;                 // 256
    float* colp = pool + 256;                // 448
    unsigned char* seg = (unsigned char*)(colp + 448); // 224

    const int tid   = threadIdx.x;
    const int ebase = g * EDGES;
    const int nbase = g * NODES;

    __syncthreads();   // smem handoff from previous phase

    // --- 1. zero C fully; zero t pad rows ---
    {
        uint4 z = {0, 0, 0, 0};
        uint4* C4 = (uint4*)C;
        for (int i = tid; i < 224 * CS * 2 / 16; i += 512) C4[i] = z;
        uint4* tp = (uint4*)(th + 200 * TSN);
        uint4* lp = (uint4*)(tl + 200 * TSN);
        for (int i = tid; i < 8 * TSN * 2 / 16; i += 512) { tp[i] = z; lp[i] = z; }
    }
    __syncthreads();

    // --- 2. count matrix via bf16x2 atomics ---
    {
        const bf16 one = __float2bfloat16(1.0f);
        const bf16 zer = __float2bfloat16(0.0f);
        __nv_bfloat162 v10 = __halves2bfloat162(one, zer);
        __nv_bfloat162 v01 = __halves2bfloat162(zer, one);
        __nv_bfloat162* C2 = (__nv_bfloat162*)C;
        for (int e = tid; e < EDGES; e += 512) {
            int sl = src[ebase + e] - nbase;
            int dl = dst[ebase + e] - nbase;
            atomicAdd(&C2[dl * (CS / 2) + (sl >> 1)], (sl & 1) ? v01 : v10);
        }
    }
    __syncthreads();

    // --- 3. row sums (2-way split) ---
    if (tid < 448) {
        int r = tid % 224, half = tid / 224;
        const __nv_bfloat162* row = (const __nv_bfloat162*)C + r * (CS / 2) + half * 54;
        float sum = 0.0f;
        for (int w = 0; w < 54; w++) {
            float2 f = __bfloat1622float2(row[w]);
            sum += f.x + f.y;
        }
        colp[tid] = sum;
    }
    __syncthreads();
    if (tid < 224) {
        float sum = colp[tid] + colp[224 + tid];
        s_a[tid]  = sum;
        s_ii[tid] = rsqrtf(fmaxf(sum, 1.0f));
    }
    __syncthreads();

    // --- 4. col sums (2-way split over rows) ---
    if (tid < 432) {
        int cc = tid % 216, half = tid / 216;
        float sum = 0.0f;
        for (int d = half * 100; d < half * 100 + 100; d++)
            sum += __bfloat162float(C[d * CS + cc]);
        colp[tid] = sum;
    }
    __syncthreads();
    if (tid < CS) {
        float sum = colp[tid] + colp[216 + tid];
        float io = rsqrtf(fmaxf(sum, 1.0f));
        s_io[tid] = io;
        s_s[tid]  = s_a[tid] * io;
    }
    __syncthreads();

    // --- wait for PWL tables ---
    if (tid == 0) {
        unsigned v;
        do {
            asm volatile("ld.global.acquire.gpu.u32 %0, [%1];"
                         : "=r"(v) : "l"(&g_pwl_flag));
            if (v < 16u) __nanosleep(64);
        } while (v < 16u);
    }
    __syncthreads();

    // --- 5. layer-1 matvec (2-way split) + segment search ---
    if (tid < 400) {
        int d = tid % 200, half = tid / 200;
        const __nv_bfloat162* row = (const __nv_bfloat162*)C + d * (CS / 2) + half * 54;
        const float2* ss2 = (const float2*)s_s + half * 54;
        float sum = 0.0f;
        for (int w = 0; w < 54; w++) {
            float2 f = __bfloat1622float2(row[w]);
            float2 s = ss2[w];
            sum = fmaf(f.x, s.x, fmaf(f.y, s.y, sum));
        }
        colp[tid] = sum;
    }
    __syncthreads();
    if (tid < NODES) {
        float a = (colp[tid] + colp[200 + tid]) * s_ii[tid];
        s_a[tid] = a;
        int lo = 0, hi = 128;
        while (lo < hi) {
            int m = (lo + hi) >> 1;
            if (g_csorted[m] < a) lo = m + 1; else hi = m;
        }
        seg[tid] = (unsigned char)lo;
    }
    __syncthreads();

    // --- 6. t hi/lo ---
    for (int idx = tid; idx < NODES * 32; idx += 512) {
        int i = idx >> 5, q = idx & 31;
        float a  = s_a[i];
        float io = s_io[i];
        int   s  = seg[i];
        float4 al = ((const float4*)(g_alpha + s * 128))[q];
        float4 be = ((const float4*)(g_beta  + s * 128))[q];
        float v0 = fmaf(al.x, a, be.x) * io;
        float v1 = fmaf(al.y, a, be.y) * io;
        float v2 = fmaf(al.z, a, be.z) * io;
        float v3 = fmaf(al.w, a, be.w) * io;
        bf16 h0 = __float2bfloat16(v0), h1 = __float2bfloat16(v1);
        bf16 h2 = __float2bfloat16(v2), h3 = __float2bfloat16(v3);
        __nv_bfloat162 hp0 = __halves2bfloat162(h0, h1);
        __nv_bfloat162 hp1 = __halves2bfloat162(h2, h3);
        __nv_bfloat162 lp0 = __halves2bfloat162(
            __float2bfloat16(v0 - __bfloat162float(h0)),
            __float2bfloat16(v1 - __bfloat162float(h1)));
        __nv_bfloat162 lp1 = __halves2bfloat162(
            __float2bfloat16(v2 - __bfloat162float(h2)),
            __float2bfloat16(v3 - __bfloat162float(h3)));
        __nv_bfloat162* dh = (__nv_bfloat162*)(th + i * TSN + q * 4);
        __nv_bfloat162* dl = (__nv_bfloat162*)(tl + i * TSN + q * 4);
        dh[0] = hp0; dh[1] = hp1;
        dl[0] = lp0; dl[1] = lp1;
    }
    __syncthreads();

    // --- 7. MMA: acc = C @ (th + tl) ---
    const int lane = tid & 31;
    const int wid  = tid >> 5;
    const int wm   = wid & 1;
    const int wn   = wid >> 1;

    float c[7][2][4];
    #pragma unroll
    for (int mi = 0; mi < 7; mi++)
        #pragma unroll
        for (int ni = 0; ni < 2; ni++)
            #pragma unroll
            for (int q = 0; q < 4; q++) c[mi][ni][q] = 0.0f;

    const int aRow = wm * 112 + (lane & 15);
    const int aCol = ((lane >> 4) & 1) * 8;
    const int bRow = (lane & 7) + ((lane >> 4) & 1) * 8;
    const int bCol = wn * 16 + ((lane >> 3) & 1) * 8;

    for (int kt = 0; kt < 13; kt++) {
        unsigned bh[4], bl[4], af[7][4];
        const int kr = kt * 16 + bRow;
        ldsm4t(bh, th + kr * TSN + bCol);
        ldsm4t(bl, tl + kr * TSN + bCol);
        #pragma unroll
        for (int mi = 0; mi < 7; mi++)
            ldsm4(af[mi], C + (aRow + mi * 16) * CS + kt * 16 + aCol);
        #pragma unroll
        for (int mi = 0; mi < 7; mi++) mma_bf16(c[mi][0], af[mi], bh[0], bh[2]);
        #pragma unroll
        for (int mi = 0; mi < 7; mi++) mma_bf16(c[mi][1], af[mi], bh[1], bh[3]);
        #pragma unroll
        for (int mi = 0; mi < 7; mi++) mma_bf16(c[mi][0], af[mi], bl[0], bl[2]);
        #pragma unroll
        for (int mi = 0; mi < 7; mi++) mma_bf16(c[mi][1], af[mi], bl[1], bl[3]);
    }

    // --- 8. epilogue: relu + fused pool ---
    {
        const int gg = lane >> 2;
        const int tg = lane & 3;
        float bx[2], by[2];
        #pragma unroll
        for (int ni = 0; ni < 2; ni++) {
            int col = wn * 16 + ni * 8 + tg * 2;
            float2 bv = *(const float2*)(b2 + col);
            bx[ni] = bv.x; by[ni] = bv.y;
        }
        float ps[2][2] = {{0, 0}, {0, 0}};
        #pragma unroll
        for (int mi = 0; mi < 7; mi++) {
            int r0 = wm * 112 + mi * 16 + gg;
            int r1 = r0 + 8;
            float ii0 = (r0 < NODES) ? s_ii[r0] : 0.0f;
            float ii1 = (r1 < NODES) ? s_ii[r1] : 0.0f;
            #pragma unroll
            for (int ni = 0; ni < 2; ni++) {
                if (r0 < NODES) {
                    ps[ni][0] += fmaxf(fmaf(c[mi][ni][0], ii0, bx[ni]), 0.0f);
                    ps[ni][1] += fmaxf(fmaf(c[mi][ni][1], ii0, by[ni]), 0.0f);
                }
                if (r1 < NODES) {
                    ps[ni][0] += fmaxf(fmaf(c[mi][ni][2], ii1, bx[ni]), 0.0f);
                    ps[ni][1] += fmaxf(fmaf(c[mi][ni][3], ii1, by[ni]), 0.0f);
                }
            }
        }
        #pragma unroll
        for (int off = 16; off >= 4; off >>= 1) {
            #pragma unroll
            for (int ni = 0; ni < 2; ni++) {
                ps[ni][0] += __shfl_down_sync(0xffffffffu, ps[ni][0], off);
                ps[ni][1] += __shfl_down_sync(0xffffffffu, ps[ni][1], off);
            }
        }
        if (lane < 4) {
            #pragma unroll
            for (int ni = 0; ni < 2; ni++) {
                int col = wn * 16 + ni * 8 + lane * 2;
                pool[wm * 128 + col]     = ps[ni][0];
                pool[wm * 128 + col + 1] = ps[ni][1];
            }
        }
    }
    __syncthreads();
    if (tid < HID) {
        float v = (pool[tid] + pool[128 + tid]) * (1.0f / 200.0f);
        bf16 h = __float2bfloat16(v);
        hgh[g * HID + tid] = h;
        hgl[g * HID + tid] = __float2bfloat16(v - __bfloat162float(h));
    }
}

// ===========================================================================
// Persistent merged kernel: grid = 148 CTAs x 512 threads, 1 CTA/SM, all
// resident. bids 0..15 build PWL; all CTAs run the conv prologue; then all
// work-steal graphs via g_gnn_ctr (balanced 512/148 distribution).
// ===========================================================================
__global__ void __launch_bounds__(512, 1) prep_gnn(
    const int* __restrict__ src, const int* __restrict__ dst,
    const float* __restrict__ W1, const float* __restrict__ b1,
    const float* __restrict__ W2, const float* __restrict__ b2,
    const float* __restrict__ Wa, const float* __restrict__ Wb,
    const float* __restrict__ Wc, const float* __restrict__ Wd,
    bf16* __restrict__ hgh, bf16* __restrict__ hgl)
{
    extern __shared__ unsigned char smraw[];
    __shared__ unsigned s_g;
    const int bid = blockIdx.x;

    if (bid < 16) pwl_block(bid, smraw, W1, b1, W2);
    conv_block(bid, 148, smraw, Wa, Wb, Wc, Wd);

    for (;;) {
        __syncthreads();
        if (threadIdx.x == 0) s_g = atomicAdd(&g_gnn_ctr, 1u);
        __syncthreads();
        unsigned g = s_g;
        if (g >= NG) break;
        gnn_block((int)g, smraw, src, dst, b2, hgh, hgl);
    }
}

// ---------------------------------------------------------------------------
// bf16 hi/lo tensor-core GEMM: 32x64 tile, 256 threads, 3-stage cp.async
// pipeline (2-tile lookahead), static SMEM 46 KB -> up to 4 CTAs/SM.
// ---------------------------------------------------------------------------
#define TSB 40

__global__ void __launch_bounds__(256) gemm_bf16(
    const bf16* __restrict__ Ah, const bf16* __restrict__ Al,
    const bf16* __restrict__ Bh, const bf16* __restrict__ Bl,
    const float* __restrict__ bias,
    bf16* __restrict__ Oh, bf16* __restrict__ Ol,
    int K, int Nc)
{
    __shared__ bf16 sAh[3][32 * TSB], sAl[3][32 * TSB];
    __shared__ bf16 sBh[3][64 * TSB], sBl[3][64 * TSB];

    const int tid  = threadIdx.x;
    const int lane = tid & 31;
    const int wid  = tid >> 5;
    const int wm   = wid & 1;           // 2 m-groups x 16 rows
    const int wn   = wid >> 1;          // 4 n-groups x 16 cols
    const int row0 = blockIdx.y * 32, col0 = blockIdx.x * 64;

    const int th  = tid & 127;
    const int lr  = th >> 2;            // 0..31
    const int lc  = (th & 3) * 8;
    const bool pl = (tid < 128);

    const bf16* gA = (pl ? Ah : Al) + (size_t)(row0 + lr) * K + lc;
    const bf16* gB = (pl ? Bh : Bl) + (size_t)(col0 + lr) * K + lc;
    bf16* const bA[3] = { (pl ? sAh[0] : sAl[0]) + lr * TSB + lc,
                          (pl ? sAh[1] : sAl[1]) + lr * TSB + lc,
                          (pl ? sAh[2] : sAl[2]) + lr * TSB + lc };
    bf16* const bB[3] = { (pl ? sBh[0] : sBl[0]) + lr * TSB + lc,
                          (pl ? sBh[1] : sBl[1]) + lr * TSB + lc,
                          (pl ? sBh[2] : sBl[2]) + lr * TSB + lc };

    float c[2][4];
    #pragma unroll
    for (int ni = 0; ni < 2; ni++)
        #pragma unroll
        for (int q = 0; q < 4; q++) c[ni][q] = 0.0f;

    const int nkt = K >> 5;

    // prologue: issue tiles 0, 1
    #pragma unroll
    for (int p = 0; p < 2; p++) {
        if (p < nkt) {
            cp16(bA[p], gA + (size_t)p * 32);
            cp16(bB[p], gB + (size_t)p * 32);
            cp16(bB[p] + 32 * TSB, gB + (size_t)p * 32 + (size_t)32 * K);
            cp_commit();
        }
    }

    const int frow = lane & 15;
    const int fk   = (lane >> 4) * 8;

    for (int kt = 0; kt < nkt; kt++) {
        if (kt + 1 < nkt) cp_wait<1>(); else cp_wait<0>();
        __syncthreads();

        // issue tile kt+2 (overwrites stage of tile kt-1, done last iter)
        if (kt + 2 < nkt) {
            int st = (kt + 2) % 3;
            cp16(bA[st], gA + (size_t)(kt + 2) * 32);
            cp16(bB[st], gB + (size_t)(kt + 2) * 32);
            cp16(bB[st] + 32 * TSB, gB + (size_t)(kt + 2) * 32 + (size_t)32 * K);
            cp_commit();
        }

        const int buf = kt % 3;
        #pragma unroll
        for (int ks = 0; ks < 32; ks += 16) {
            unsigned ah[4], al[4], bh[4], bl[4];
            {
                int ro = (wm * 16 + frow) * TSB + ks + fk;
                ldsm4(ah, &sAh[buf][ro]);
                ldsm4(al, &sAl[buf][ro]);
            }
            {
                int no = (wn * 16 + frow) * TSB + ks + fk;
                ldsm4(bh, &sBh[buf][no]);
                ldsm4(bl, &sBl[buf][no]);
            }
            mma_bf16(c[0], ah, bh[0], bh[2]);
            mma_bf16(c[1], ah, bh[1], bh[3]);
            mma_bf16(c[0], ah, bl[0], bl[2]);
            mma_bf16(c[1], ah, bl[1], bl[3]);
            mma_bf16(c[0], al, bh[0], bh[2]);
            mma_bf16(c[1], al, bh[1], bh[3]);
        }
        __syncthreads();
    }

    const int g  = lane >> 2;
    const int tg = lane & 3;
    #pragma unroll
    for (int ni = 0; ni < 2; ni++) {
        int r  = row0 + wm * 16 + g;
        int cc = col0 + wn * 16 + ni * 8 + tg * 2;
        float2 bv = *(const float2*)(bias + cc);
        #pragma unroll
        for (int half = 0; half < 2; half++) {
            int rr = r + half * 8;
            float vx = fmaxf(c[ni][half * 2 + 0] + bv.x, 0.0f);
            float vy = fmaxf(c[ni][half * 2 + 1] + bv.y, 0.0f);
            bf16 hx = __float2bfloat16(vx);
            bf16 hy = __float2bfloat16(vy);
            __nv_bfloat162 hp(hx, hy);
            __nv_bfloat162 lp(__float2bfloat16(vx - __bfloat162float(hx)),
                              __float2bfloat16(vy - __bfloat162float(hy)));
            *(__nv_bfloat162*)(Oh + (size_t)rr * Nc + cc) = hp;
            *(__nv_bfloat162*)(Ol + (size_t)rr * Nc + cc) = lp;
        }
    }
}

// ---------------------------------------------------------------------------
// Final layer + cross-kernel state reset for the next replay.
// ---------------------------------------------------------------------------
__global__ void __launch_bounds__(256) head_softmax(
    const bf16* __restrict__ Ah, const bf16* __restrict__ Al,
    const float* __restrict__ We, const float* __restrict__ be,
    float* __restrict__ out)
{
    if (blockIdx.x == 0 && threadIdx.x == 0) {
        g_pwl_flag = 0;
        g_gnn_ctr  = 0;
    }

    __shared__ float Ws[512 * 10];
    const int tid = threadIdx.x;
    for (int i = tid; i < 512 * 10; i += 256) Ws[i] = We[i];
    __syncthreads();
    const int lane = tid & 31, w = tid >> 5;
    const int row = blockIdx.x * 8 + w;

    float acc[10];
    #pragma unroll
    for (int c = 0; c < 10; c++) acc[c] = 0.0f;
    for (int k = lane; k < 512; k += 32) {
        float a = __bfloat162float(Ah[row * 512 + k]) +
                  __bfloat162float(Al[row * 512 + k]);
        #pragma unroll
        for (int c = 0; c < 10; c++) acc[c] = fmaf(a, Ws[k * 10 + c], acc[c]);
    }
    #pragma unroll
    for (int c = 0; c < 10; c++) {
        #pragma unroll
        for (int o = 16; o > 0; o >>= 1)
            acc[c] += __shfl_xor_sync(0xffffffffu, acc[c], o);
    }
    if (lane == 0) {
        float v[10], mx = -1e30f;
        #pragma unroll
        for (int c = 0; c < 10; c++) { v[c] = acc[c] + be[c]; mx = fmaxf(mx, v[c]); }
        float s = 0.0f;
        #pragma unroll
        for (int c = 0; c < 10; c++) { v[c] = __expf(v[c] - mx); s += v[c]; }
        float inv = 1.0f / s;
        #pragma unroll
        for (int c = 0; c < 10; c++) out[row * 10 + c] = v[c] * inv;
    }
}

// ---------------------------------------------------------------------------
extern "C" void kernel_launch(void* const* d_in, const int* in_sizes, int n_in,
                              void* d_out, int out_size)
{
    const int*   src = (const int*)  d_in[0];
    const int*   dst = (const int*)  d_in[1];
    const float* W1  = (const float*)d_in[2];
    const float* b1  = (const float*)d_in[3];
    const float* W2  = (const float*)d_in[4];
    const float* b2  = (const float*)d_in[5];
    const float* Wa  = (const float*)d_in[6];
    const float* ba  = (const float*)d_in[7];
    const float* Wb  = (const float*)d_in[8];
    const float* bb  = (const float*)d_in[9];
    const float* Wc  = (const float*)d_in[10];
    const float* bc  = (const float*)d_in[11];
    const float* Wd  = (const float*)d_in[12];
    const float* bd  = (const float*)d_in[13];
    const float* We  = (const float*)d_in[14];
    const float* be  = (const float*)d_in[15];
    float* out = (float*)d_out;

    bf16 *hgh, *hgl, *x1h, *x1l, *x2h, *x2l, *x3h, *x3l, *x4h, *x4l;
    bf16 *wah, *wal, *wbh, *wbl, *wch, *wcl, *wdh, *wdl;
    cudaGetSymbolAddress((void**)&hgh, g_hgh); cudaGetSymbolAddress((void**)&hgl, g_hgl);
    cudaGetSymbolAddress((void**)&x1h, g_x1h); cudaGetSymbolAddress((void**)&x1l, g_x1l);
    cudaGetSymbolAddress((void**)&x2h, g_x2h); cudaGetSymbolAddress((void**)&x2l, g_x2l);
    cudaGetSymbolAddress((void**)&x3h, g_x3h); cudaGetSymbolAddress((void**)&x3l, g_x3l);
    cudaGetSymbolAddress((void**)&x4h, g_x4h); cudaGetSymbolAddress((void**)&x4l, g_x4l);
    cudaGetSymbolAddress((void**)&wah, g_wta_h); cudaGetSymbolAddress((void**)&wal, g_wta_l);
    cudaGetSymbolAddress((void**)&wbh, g_wtb_h); cudaGetSymbolAddress((void**)&wbl, g_wtb_l);
    cudaGetSymbolAddress((void**)&wch, g_wtc_h); cudaGetSymbolAddress((void**)&wcl, g_wtc_l);
    cudaGetSymbolAddress((void**)&wdh, g_wtd_h); cudaGetSymbolAddress((void**)&wdl, g_wtd_l);

    const int SMEM = 224 * CS * 2 + 2 * 208 * TSN * 2
                   + 4 * 224 * 4 + 256 * 4 + 448 * 4 + 224;
    cudaFuncSetAttribute(prep_gnn, cudaFuncAttributeMaxDynamicSharedMemorySize, SMEM);

    prep_gnn<<<148, 512, SMEM>>>(src, dst, W1, b1, W2, b2, Wa, Wb, Wc, Wd, hgh, hgl);

    gemm_bf16<<<dim3(512 / 64,  512 / 32), 256>>>(hgh, hgl, wah, wal, ba, x1h, x1l, 128,  512);
    gemm_bf16<<<dim3(1024 / 64, 512 / 32), 256>>>(x1h, x1l, wbh, wbl, bb, x2h, x2l, 512,  1024);
    gemm_bf16<<<dim3(1024 / 64, 512 / 32), 256>>>(x2h, x2l, wch, wcl, bc, x3h, x3l, 1024, 1024);
    gemm_bf16<<<dim3(512 / 64,  512 / 32), 256>>>(x3h, x3l, wdh, wdl, bd, x4h, x4l, 1024, 512);

    head_softmax<<<64, 256>>>(x4h, x4l, We, be, out);
}

// round 12
// speedup vs baseline: 1.0097x; 1.0002x over previous
#include <cuda_runtime.h>
#include <cuda_bf16.h>

#define NG      512
#define NODES   200
#define EDGES   6400
#define HID     128

typedef __nv_bfloat16 bf16;

// ---- activation buffers (bf16 hi/lo pairs) --------------------------------
__device__ bf16 g_hgh[NG * HID],  g_hgl[NG * HID];
__device__ bf16 g_x1h[NG * 512],  g_x1l[NG * 512];
__device__ bf16 g_x2h[NG * 1024], g_x2l[NG * 1024];
__device__ bf16 g_x3h[NG * 1024], g_x3l[NG * 1024];
__device__ bf16 g_x4h[NG * 512],  g_x4l[NG * 512];

// ---- pre-converted transposed weights [N][K] bf16 hi/lo -------------------
__device__ bf16 g_wta_h[512 * 128],   g_wta_l[512 * 128];
__device__ bf16 g_wtb_h[1024 * 512],  g_wtb_l[1024 * 512];
__device__ bf16 g_wtc_h[1024 * 1024], g_wtc_l[1024 * 1024];
__device__ bf16 g_wtd_h[512 * 1024],  g_wtd_l[512 * 1024];

// ---- split-K partial scratch (fp32) ----------------------------------------
__device__ float g_part[4 * 512 * 1024];

// ---- PWL tables + cross-kernel state (reset by head_softmax each launch) --
__device__ float g_csorted[128];
__device__ float g_alpha[129 * 128];
__device__ float g_beta[129 * 128];
__device__ unsigned g_pwl_flag = 0;
__device__ unsigned g_gnn_ctr  = 0;

// ---- asm helpers -----------------------------------------------------------
__device__ __forceinline__ void cp16(void* smem, const void* gmem) {
    unsigned sa = (unsigned)__cvta_generic_to_shared(smem);
    asm volatile("cp.async.cg.shared.global [%0], [%1], 16;\n" :: "r"(sa), "l"(gmem));
}
__device__ __forceinline__ void cp_commit() {
    asm volatile("cp.async.commit_group;\n");
}
template <int N>
__device__ __forceinline__ void cp_wait() {
    asm volatile("cp.async.wait_group %0;\n" :: "n"(N));
}
__device__ __forceinline__ void ldsm4(unsigned r[4], const void* p) {
    unsigned a = (unsigned)__cvta_generic_to_shared(p);
    asm volatile("ldmatrix.sync.aligned.m8n8.x4.shared.b16 {%0,%1,%2,%3}, [%4];\n"
                 : "=r"(r[0]), "=r"(r[1]), "=r"(r[2]), "=r"(r[3]) : "r"(a));
}
__device__ __forceinline__ void ldsm4t(unsigned r[4], const void* p) {
    unsigned a = (unsigned)__cvta_generic_to_shared(p);
    asm volatile("ldmatrix.sync.aligned.m8n8.x4.trans.shared.b16 {%0,%1,%2,%3}, [%4];\n"
                 : "=r"(r[0]), "=r"(r[1]), "=r"(r[2]), "=r"(r[3]) : "r"(a));
}
__device__ __forceinline__ void mma_bf16(float c[4], const unsigned a[4],
                                         unsigned b0, unsigned b1) {
    asm volatile(
        "mma.sync.aligned.m16n8k16.row.col.f32.bf16.bf16.f32 "
        "{%0,%1,%2,%3}, {%4,%5,%6,%7}, {%8,%9}, {%0,%1,%2,%3};\n"
        : "+f"(c[0]), "+f"(c[1]), "+f"(c[2]), "+f"(c[3])
        : "r"(a[0]), "r"(a[1]), "r"(a[2]), "r"(a[3]), "r"(b0), "r"(b1));
}

// ===========================================================================
// PWL table builder (bids 0..15, 8 segments each). tid<128 active.
// ===========================================================================
__device__ void pwl_block(int p, unsigned char* smraw,
    const float* __restrict__ W1, const float* __restrict__ b1,
    const float* __restrict__ W2)
{
    float* sW2 = (float*)smraw;            // 16384 floats
    float* sc  = sW2 + 16384;
    float* sw  = sc + 128;
    float* sb  = sw + 128;
    float* ssc = sb + 128;
    int*  sidx = (int*)(ssc + 128);
    const int tid = threadIdx.x;

    for (int i = tid; i < 4096; i += 512)
        ((float4*)sW2)[i] = ((const float4*)W2)[i];
    if (tid < 128) {
        float w = W1[tid], b = b1[tid];
        sw[tid] = w; sb[tid] = b;
        sc[tid] = (w != 0.0f) ? (-b / w) : __int_as_float(0x7f800000);
    }
    __syncthreads();
    if (tid < 128) {
        float c = sc[tid];
        int r = 0;
        for (int j = 0; j < 128; j++) {
            float cj = sc[j];
            if (cj < c || (cj == c && j < tid)) r++;
        }
        sidx[r] = tid;
        ssc[r]  = c;
    }
    __syncthreads();
    if (tid < 128) {
        if (p == 0) g_csorted[tid] = ssc[tid];
        const int j  = tid;
        const int s0 = p * 8;
        float alpha = 0.0f, beta = 0.0f;
        for (int r = 0; r < 128; r++) {
            int k = sidx[r];
            float w = sw[k], b = sb[k];
            float W2kj = sW2[k * 128 + j];
            if (w == 0.0f) { if (b > 0.0f) beta += b * W2kj; continue; }
            bool active = (w > 0.0f) ? (r < s0) : (r >= s0);
            if (active) { alpha = fmaf(w, W2kj, alpha); beta = fmaf(b, W2kj, beta); }
        }
        for (int s = s0; s < s0 + 8; s++) {
            g_alpha[s * 128 + j] = alpha;
            g_beta[s * 128 + j]  = beta;
            int k = sidx[s];
            float w = sw[k], b = sb[k];
            float W2kj = sW2[k * 128 + j];
            float f = (w > 0.0f) ? 1.0f : ((w < 0.0f) ? -1.0f : 0.0f);
            alpha = fmaf(f * w, W2kj, alpha);
            beta  = fmaf(f * b, W2kj, beta);
        }
        if (p == 15) {
            g_alpha[128 * 128 + j] = alpha;
            g_beta[128 * 128 + j]  = beta;
        }
    }
    __syncthreads();
    if (tid == 0) {
        __threadfence();
        atomicAdd(&g_pwl_flag, 1u);
    }
}

// ===========================================================================
// Weight-convert prologue: grid-stride over 2112 32x32 transpose tiles.
// ===========================================================================
__device__ void conv_block(int w, int stride, unsigned char* smraw,
    const float* __restrict__ Wa, const float* __restrict__ Wb,
    const float* __restrict__ Wc, const float* __restrict__ Wd)
{
    float (*tile)[33] = (float(*)[33])smraw;
    const int tid = threadIdx.x;
    const int c = tid & 31, r = tid >> 5;   // r: 0..15

    for (int t = w; t < 2112; t += stride) {
        const float* W; bf16 *Oh, *Ol; int K, N, tl, tn;
        if (t < 64)        { W = Wa; Oh = g_wta_h; Ol = g_wta_l; K = 128;  N = 512;  tl = t;        tn = 16; }
        else if (t < 576)  { W = Wb; Oh = g_wtb_h; Ol = g_wtb_l; K = 512;  N = 1024; tl = t - 64;   tn = 32; }
        else if (t < 1600) { W = Wc; Oh = g_wtc_h; Ol = g_wtc_l; K = 1024; N = 1024; tl = t - 576;  tn = 32; }
        else               { W = Wd; Oh = g_wtd_h; Ol = g_wtd_l; K = 1024; N = 512;  tl = t - 1600; tn = 16; }
        int nb = (tl % tn) * 32, kb = (tl / tn) * 32;
        #pragma unroll
        for (int j = 0; j < 2; j++)
            tile[r + j * 16][c] = W[(size_t)(kb + r + j * 16) * N + nb + c];
        __syncthreads();
        #pragma unroll
        for (int j = 0; j < 2; j++) {
            int n = nb + r + j * 16;
            float v = tile[c][r + j * 16];
            bf16 h = __float2bfloat16(v);
            Oh[(size_t)n * K + kb + c] = h;
            Ol[(size_t)n * K + kb + c] = __float2bfloat16(v - __bfloat162float(h));
        }
        __syncthreads();
    }
}

// ===========================================================================
// Per-graph GNN block (dense count-matrix + tensor-core SpMM).
// SMEM = 216,544 B
// ===========================================================================
#define CS 216
#define TSN 136

__device__ void gnn_block(int g, unsigned char* smraw,
    const int* __restrict__ src, const int* __restrict__ dst,
    const float* __restrict__ b2,
    bf16* __restrict__ hgh, bf16* __restrict__ hgl)
{
    bf16*  C    = (bf16*)smraw;
    bf16*  th   = C + 224 * CS;
    bf16*  tl   = th + 208 * TSN;
    float* s_a  = (float*)(tl + 208 * TSN);
    float* s_ii = s_a + 224;
    float* s_io = s_ii + 224;
    float* s_s  = s_io + 224;
    float* pool = s_s + 224;                 // 256
    float* colp = pool + 256;                // 448
    unsigned char* seg = (unsigned char*)(colp + 448); // 224

    const int tid   = threadIdx.x;
    const int ebase = g * EDGES;
    const int nbase = g * NODES;

    __syncthreads();   // smem handoff from previous phase

    // --- 1. zero C fully; zero t pad rows ---
    {
        uint4 z = {0, 0, 0, 0};
        uint4* C4 = (uint4*)C;
        for (int i = tid; i < 224 * CS * 2 / 16; i += 512) C4[i] = z;
        uint4* tp = (uint4*)(th + 200 * TSN);
        uint4* lp = (uint4*)(tl + 200 * TSN);
        for (int i = tid; i < 8 * TSN * 2 / 16; i += 512) { tp[i] = z; lp[i] = z; }
    }
    __syncthreads();

    // --- 2. count matrix via bf16x2 atomics ---
    {
        const bf16 one = __float2bfloat16(1.0f);
        const bf16 zer = __float2bfloat16(0.0f);
        __nv_bfloat162 v10 = __halves2bfloat162(one, zer);
        __nv_bfloat162 v01 = __halves2bfloat162(zer, one);
        __nv_bfloat162* C2 = (__nv_bfloat162*)C;
        for (int e = tid; e < EDGES; e += 512) {
            int sl = src[ebase + e] - nbase;
            int dl = dst[ebase + e] - nbase;
            atomicAdd(&C2[dl * (CS / 2) + (sl >> 1)], (sl & 1) ? v01 : v10);
        }
    }
    __syncthreads();

    // --- 3. row sums (2-way split) ---
    if (tid < 448) {
        int r = tid % 224, half = tid / 224;
        const __nv_bfloat162* row = (const __nv_bfloat162*)C + r * (CS / 2) + half * 54;
        float sum = 0.0f;
        for (int w = 0; w < 54; w++) {
            float2 f = __bfloat1622float2(row[w]);
            sum += f.x + f.y;
        }
        colp[tid] = sum;
    }
    __syncthreads();
    if (tid < 224) {
        float sum = colp[tid] + colp[224 + tid];
        s_a[tid]  = sum;
        s_ii[tid] = rsqrtf(fmaxf(sum, 1.0f));
    }
    __syncthreads();

    // --- 4. col sums (2-way split over rows) ---
    if (tid < 432) {
        int cc = tid % 216, half = tid / 216;
        float sum = 0.0f;
        for (int d = half * 100; d < half * 100 + 100; d++)
            sum += __bfloat162float(C[d * CS + cc]);
        colp[tid] = sum;
    }
    __syncthreads();
    if (tid < CS) {
        float sum = colp[tid] + colp[216 + tid];
        float io = rsqrtf(fmaxf(sum, 1.0f));
        s_io[tid] = io;
        s_s[tid]  = s_a[tid] * io;
    }
    __syncthreads();

    // --- wait for PWL tables ---
    if (tid == 0) {
        unsigned v;
        do {
            asm volatile("ld.global.acquire.gpu.u32 %0, [%1];"
                         : "=r"(v) : "l"(&g_pwl_flag));
            if (v < 16u) __nanosleep(64);
        } while (v < 16u);
    }
    __syncthreads();

    // --- 5. layer-1 matvec (2-way split) + segment search ---
    if (tid < 400) {
        int d = tid % 200, half = tid / 200;
        const __nv_bfloat162* row = (const __nv_bfloat162*)C + d * (CS / 2) + half * 54;
        const float2* ss2 = (const float2*)s_s + half * 54;
        float sum = 0.0f;
        for (int w = 0; w < 54; w++) {
            float2 f = __bfloat1622float2(row[w]);
            float2 s = ss2[w];
            sum = fmaf(f.x, s.x, fmaf(f.y, s.y, sum));
        }
        colp[tid] = sum;
    }
    __syncthreads();
    if (tid < NODES) {
        float a = (colp[tid] + colp[200 + tid]) * s_ii[tid];
        s_a[tid] = a;
        int lo = 0, hi = 128;
        while (lo < hi) {
            int m = (lo + hi) >> 1;
            if (g_csorted[m] < a) lo = m + 1; else hi = m;
        }
        seg[tid] = (unsigned char)lo;
    }
    __syncthreads();

    // --- 6. t hi/lo ---
    for (int idx = tid; idx < NODES * 32; idx += 512) {
        int i = idx >> 5, q = idx & 31;
        float a  = s_a[i];
        float io = s_io[i];
        int   s  = seg[i];
        float4 al = ((const float4*)(g_alpha + s * 128))[q];
        float4 be = ((const float4*)(g_beta  + s * 128))[q];
        float v0 = fmaf(al.x, a, be.x) * io;
        float v1 = fmaf(al.y, a, be.y) * io;
        float v2 = fmaf(al.z, a, be.z) * io;
        float v3 = fmaf(al.w, a, be.w) * io;
        bf16 h0 = __float2bfloat16(v0), h1 = __float2bfloat16(v1);
        bf16 h2 = __float2bfloat16(v2), h3 = __float2bfloat16(v3);
        __nv_bfloat162 hp0 = __halves2bfloat162(h0, h1);
        __nv_bfloat162 hp1 = __halves2bfloat162(h2, h3);
        __nv_bfloat162 lp0 = __halves2bfloat162(
            __float2bfloat16(v0 - __bfloat162float(h0)),
            __float2bfloat16(v1 - __bfloat162float(h1)));
        __nv_bfloat162 lp1 = __halves2bfloat162(
            __float2bfloat16(v2 - __bfloat162float(h2)),
            __float2bfloat16(v3 - __bfloat162float(h3)));
        __nv_bfloat162* dh = (__nv_bfloat162*)(th + i * TSN + q * 4);
        __nv_bfloat162* dl = (__nv_bfloat162*)(tl + i * TSN + q * 4);
        dh[0] = hp0; dh[1] = hp1;
        dl[0] = lp0; dl[1] = lp1;
    }
    __syncthreads();

    // --- 7. MMA: acc = C @ (th + tl) ---
    const int lane = tid & 31;
    const int wid  = tid >> 5;
    const int wm   = wid & 1;
    const int wn   = wid >> 1;

    float c[7][2][4];
    #pragma unroll
    for (int mi = 0; mi < 7; mi++)
        #pragma unroll
        for (int ni = 0; ni < 2; ni++)
            #pragma unroll
            for (int q = 0; q < 4; q++) c[mi][ni][q] = 0.0f;

    const int aRow = wm * 112 + (lane & 15);
    const int aCol = ((lane >> 4) & 1) * 8;
    const int bRow = (lane & 7) + ((lane >> 4) & 1) * 8;
    const int bCol = wn * 16 + ((lane >> 3) & 1) * 8;

    for (int kt = 0; kt < 13; kt++) {
        unsigned bh[4], bl[4], af[7][4];
        const int kr = kt * 16 + bRow;
        ldsm4t(bh, th + kr * TSN + bCol);
        ldsm4t(bl, tl + kr * TSN + bCol);
        #pragma unroll
        for (int mi = 0; mi < 7; mi++)
            ldsm4(af[mi], C + (aRow + mi * 16) * CS + kt * 16 + aCol);
        #pragma unroll
        for (int mi = 0; mi < 7; mi++) mma_bf16(c[mi][0], af[mi], bh[0], bh[2]);
        #pragma unroll
        for (int mi = 0; mi < 7; mi++) mma_bf16(c[mi][1], af[mi], bh[1], bh[3]);
        #pragma unroll
        for (int mi = 0; mi < 7; mi++) mma_bf16(c[mi][0], af[mi], bl[0], bl[2]);
        #pragma unroll
        for (int mi = 0; mi < 7; mi++) mma_bf16(c[mi][1], af[mi], bl[1], bl[3]);
    }

    // --- 8. epilogue: relu + fused pool ---
    {
        const int gg = lane >> 2;
        const int tg = lane & 3;
        float bx[2], by[2];
        #pragma unroll
        for (int ni = 0; ni < 2; ni++) {
            int col = wn * 16 + ni * 8 + tg * 2;
            float2 bv = *(const float2*)(b2 + col);
            bx[ni] = bv.x; by[ni] = bv.y;
        }
        float ps[2][2] = {{0, 0}, {0, 0}};
        #pragma unroll
        for (int mi = 0; mi < 7; mi++) {
            int r0 = wm * 112 + mi * 16 + gg;
            int r1 = r0 + 8;
            float ii0 = (r0 < NODES) ? s_ii[r0] : 0.0f;
            float ii1 = (r1 < NODES) ? s_ii[r1] : 0.0f;
            #pragma unroll
            for (int ni = 0; ni < 2; ni++) {
                if (r0 < NODES) {
                    ps[ni][0] += fmaxf(fmaf(c[mi][ni][0], ii0, bx[ni]), 0.0f);
                    ps[ni][1] += fmaxf(fmaf(c[mi][ni][1], ii0, by[ni]), 0.0f);
                }
                if (r1 < NODES) {
                    ps[ni][0] += fmaxf(fmaf(c[mi][ni][2], ii1, bx[ni]), 0.0f);
                    ps[ni][1] += fmaxf(fmaf(c[mi][ni][3], ii1, by[ni]), 0.0f);
                }
            }
        }
        #pragma unroll
        for (int off = 16; off >= 4; off >>= 1) {
            #pragma unroll
            for (int ni = 0; ni < 2; ni++) {
                ps[ni][0] += __shfl_down_sync(0xffffffffu, ps[ni][0], off);
                ps[ni][1] += __shfl_down_sync(0xffffffffu, ps[ni][1], off);
            }
        }
        if (lane < 4) {
            #pragma unroll
            for (int ni = 0; ni < 2; ni++) {
                int col = wn * 16 + ni * 8 + lane * 2;
                pool[wm * 128 + col]     = ps[ni][0];
                pool[wm * 128 + col + 1] = ps[ni][1];
            }
        }
    }
    __syncthreads();
    if (tid < HID) {
        float v = (pool[tid] + pool[128 + tid]) * (1.0f / 200.0f);
        bf16 h = __float2bfloat16(v);
        hgh[g * HID + tid] = h;
        hgl[g * HID + tid] = __float2bfloat16(v - __bfloat162float(h));
    }
}

// ===========================================================================
// Persistent merged kernel: grid = 148 CTAs x 512 threads (all resident).
// ===========================================================================
__global__ void __launch_bounds__(512, 1) prep_gnn(
    const int* __restrict__ src, const int* __restrict__ dst,
    const float* __restrict__ W1, const float* __restrict__ b1,
    const float* __restrict__ W2, const float* __restrict__ b2,
    const float* __restrict__ Wa, const float* __restrict__ Wb,
    const float* __restrict__ Wc, const float* __restrict__ Wd,
    bf16* __restrict__ hgh, bf16* __restrict__ hgl)
{
    extern __shared__ unsigned char smraw[];
    __shared__ unsigned s_g;
    const int bid = blockIdx.x;

    if (bid < 16) pwl_block(bid, smraw, W1, b1, W2);
    conv_block(bid, 148, smraw, Wa, Wb, Wc, Wd);

    for (;;) {
        __syncthreads();
        if (threadIdx.x == 0) s_g = atomicAdd(&g_gnn_ctr, 1u);
        __syncthreads();
        unsigned g = s_g;
        if (g >= NG) break;
        gnn_block((int)g, smraw, src, dst, b2, hgh, hgl);
    }
}

// ---------------------------------------------------------------------------
// Split-K bf16 hi/lo tensor-core GEMM: 32x64 tile, 256 threads, 2-stage
// pipeline, fp32 partial output to g_part[z]. Grid z = split chunks.
// ---------------------------------------------------------------------------
#define TSB 40

__global__ void __launch_bounds__(256) gemm_bf16(
    const bf16* __restrict__ Ah, const bf16* __restrict__ Al,
    const bf16* __restrict__ Bh, const bf16* __restrict__ Bl,
    float* __restrict__ part,
    int Ktot, int Kchunk, int Nc)
{
    __shared__ bf16 sAh[2][32 * TSB], sAl[2][32 * TSB];
    __shared__ bf16 sBh[2][64 * TSB], sBl[2][64 * TSB];

    const int tid  = threadIdx.x;
    const int lane = tid & 31;
    const int wid  = tid >> 5;
    const int wm   = wid & 1;           // 2 m-groups x 16 rows
    const int wn   = wid >> 1;          // 4 n-groups x 16 cols
    const int row0 = blockIdx.y * 32, col0 = blockIdx.x * 64;
    const int z    = blockIdx.z;
    const int kofs = z * Kchunk;

    const int th  = tid & 127;
    const int lr  = th >> 2;            // 0..31
    const int lc  = (th & 3) * 8;
    const bool pl = (tid < 128);

    const bf16* gA  = (pl ? Ah : Al) + (size_t)(row0 + lr) * Ktot + kofs + lc;
    const bf16* gB0 = (pl ? Bh : Bl) + (size_t)(col0 + lr) * Ktot + kofs + lc;
    const bf16* gB1 = (pl ? Bh : Bl) + (size_t)(col0 + 32 + lr) * Ktot + kofs + lc;
    bf16* dA0 = (pl ? sAh[0] : sAl[0]) + lr * TSB + lc;
    bf16* dB0 = (pl ? sBh[0] : sBl[0]) + lr * TSB + lc;
    bf16* dA1 = (pl ? sAh[1] : sAl[1]) + lr * TSB + lc;
    bf16* dB1 = (pl ? sBh[1] : sBl[1]) + lr * TSB + lc;

    float c[2][4];
    #pragma unroll
    for (int ni = 0; ni < 2; ni++)
        #pragma unroll
        for (int q = 0; q < 4; q++) c[ni][q] = 0.0f;

    cp16(dA0, gA);
    cp16(dB0, gB0);
    cp16(dB0 + 32 * TSB, gB1);
    cp_commit();

    const int nkt = Kchunk >> 5;
    const int frow = lane & 15;
    const int fk   = (lane >> 4) * 8;
    int buf = 0;

    for (int kt = 0; kt < nkt; kt++) {
        if (kt + 1 < nkt) {
            bf16* dA = buf ? dA0 : dA1;
            bf16* dB = buf ? dB0 : dB1;
            cp16(dA, gA + (size_t)(kt + 1) * 32);
            cp16(dB, gB0 + (size_t)(kt + 1) * 32);
            cp16(dB + 32 * TSB, gB1 + (size_t)(kt + 1) * 32);
            cp_commit();
            cp_wait<1>();
        } else {
            cp_wait<0>();
        }
        __syncthreads();

        #pragma unroll
        for (int ks = 0; ks < 32; ks += 16) {
            unsigned ah[4], al[4], bh[4], bl[4];
            {
                int ro = (wm * 16 + frow) * TSB + ks + fk;
                ldsm4(ah, &sAh[buf][ro]);
                ldsm4(al, &sAl[buf][ro]);
            }
            {
                int no = (wn * 16 + frow) * TSB + ks + fk;
                ldsm4(bh, &sBh[buf][no]);
                ldsm4(bl, &sBl[buf][no]);
            }
            mma_bf16(c[0], ah, bh[0], bh[2]);
            mma_bf16(c[1], ah, bh[1], bh[3]);
            mma_bf16(c[0], ah, bl[0], bl[2]);
            mma_bf16(c[1], ah, bl[1], bl[3]);
            mma_bf16(c[0], al, bh[0], bh[2]);
            mma_bf16(c[1], al, bh[1], bh[3]);
        }
        __syncthreads();
        buf ^= 1;
    }

    // fp32 partial epilogue
    float* po = part + (size_t)z * 512 * Nc;
    const int g  = lane >> 2;
    const int tg = lane & 3;
    #pragma unroll
    for (int ni = 0; ni < 2; ni++) {
        int r  = row0 + wm * 16 + g;
        int cc = col0 + wn * 16 + ni * 8 + tg * 2;
        *(float2*)(po + (size_t)r * Nc + cc)       = make_float2(c[ni][0], c[ni][1]);
        *(float2*)(po + (size_t)(r + 8) * Nc + cc) = make_float2(c[ni][2], c[ni][3]);
    }
}

// ---------------------------------------------------------------------------
// Combine split-K partials: out = relu(sum_s part[s] + bias) -> bf16 hi/lo.
// ---------------------------------------------------------------------------
__global__ void __launch_bounds__(256) combine_relu(
    const float* __restrict__ part, int S, int zstride,
    const float* __restrict__ bias,
    bf16* __restrict__ Oh, bf16* __restrict__ Ol,
    int Nc, int total)
{
    int i2 = (blockIdx.x * 256 + threadIdx.x) * 2;
    if (i2 >= total) return;
    float2 s = *(const float2*)(part + i2);
    for (int z = 1; z < S; z++) {
        float2 p = *(const float2*)(part + (size_t)z * zstride + i2);
        s.x += p.x; s.y += p.y;
    }
    int col = i2 % Nc;
    float2 bv = *(const float2*)(bias + col);
    float vx = fmaxf(s.x + bv.x, 0.0f);
    float vy = fmaxf(s.y + bv.y, 0.0f);
    bf16 hx = __float2bfloat16(vx);
    bf16 hy = __float2bfloat16(vy);
    *(__nv_bfloat162*)(Oh + i2) = __halves2bfloat162(hx, hy);
    *(__nv_bfloat162*)(Ol + i2) = __halves2bfloat162(
        __float2bfloat16(vx - __bfloat162float(hx)),
        __float2bfloat16(vy - __bfloat162float(hy)));
}

// ---------------------------------------------------------------------------
// Final layer + cross-kernel state reset for the next replay.
// ---------------------------------------------------------------------------
__global__ void __launch_bounds__(256) head_softmax(
    const bf16* __restrict__ Ah, const bf16* __restrict__ Al,
    const float* __restrict__ We, const float* __restrict__ be,
    float* __restrict__ out)
{
    if (blockIdx.x == 0 && threadIdx.x == 0) {
        g_pwl_flag = 0;
        g_gnn_ctr  = 0;
    }

    __shared__ float Ws[512 * 10];
    const int tid = threadIdx.x;
    for (int i = tid; i < 512 * 10; i += 256) Ws[i] = We[i];
    __syncthreads();
    const int lane = tid & 31, w = tid >> 5;
    const int row = blockIdx.x * 8 + w;

    float acc[10];
    #pragma unroll
    for (int c = 0; c < 10; c++) acc[c] = 0.0f;
    for (int k = lane; k < 512; k += 32) {
        float a = __bfloat162float(Ah[row * 512 + k]) +
                  __bfloat162float(Al[row * 512 + k]);
        #pragma unroll
        for (int c = 0; c < 10; c++) acc[c] = fmaf(a, Ws[k * 10 + c], acc[c]);
    }
    #pragma unroll
    for (int c = 0; c < 10; c++) {
        #pragma unroll
        for (int o = 16; o > 0; o >>= 1)
            acc[c] += __shfl_xor_sync(0xffffffffu, acc[c], o);
    }
    if (lane == 0) {
        float v[10], mx = -1e30f;
        #pragma unroll
        for (int c = 0; c < 10; c++) { v[c] = acc[c] + be[c]; mx = fmaxf(mx, v[c]); }
        float s = 0.0f;
        #pragma unroll
        for (int c = 0; c < 10; c++) { v[c] = __expf(v[c] - mx); s += v[c]; }
        float inv = 1.0f / s;
        #pragma unroll
        for (int c = 0; c < 10; c++) out[row * 10 + c] = v[c] * inv;
    }
}

// ---------------------------------------------------------------------------
extern "C" void kernel_launch(void* const* d_in, const int* in_sizes, int n_in,
                              void* d_out, int out_size)
{
    const int*   src = (const int*)  d_in[0];
    const int*   dst = (const int*)  d_in[1];
    const float* W1  = (const float*)d_in[2];
    const float* b1  = (const float*)d_in[3];
    const float* W2  = (const float*)d_in[4];
    const float* b2  = (const float*)d_in[5];
    const float* Wa  = (const float*)d_in[6];
    const float* ba  = (const float*)d_in[7];
    const float* Wb  = (const float*)d_in[8];
    const float* bb  = (const float*)d_in[9];
    const float* Wc  = (const float*)d_in[10];
    const float* bc  = (const float*)d_in[11];
    const float* Wd  = (const float*)d_in[12];
    const float* bd  = (const float*)d_in[13];
    const float* We  = (const float*)d_in[14];
    const float* be  = (const float*)d_in[15];
    float* out = (float*)d_out;

    bf16 *hgh, *hgl, *x1h, *x1l, *x2h, *x2l, *x3h, *x3l, *x4h, *x4l;
    bf16 *wah, *wal, *wbh, *wbl, *wch, *wcl, *wdh, *wdl;
    float* part;
    cudaGetSymbolAddress((void**)&hgh, g_hgh); cudaGetSymbolAddress((void**)&hgl, g_hgl);
    cudaGetSymbolAddress((void**)&x1h, g_x1h); cudaGetSymbolAddress((void**)&x1l, g_x1l);
    cudaGetSymbolAddress((void**)&x2h, g_x2h); cudaGetSymbolAddress((void**)&x2l, g_x2l);
    cudaGetSymbolAddress((void**)&x3h, g_x3h); cudaGetSymbolAddress((void**)&x3l, g_x3l);
    cudaGetSymbolAddress((void**)&x4h, g_x4h); cudaGetSymbolAddress((void**)&x4l, g_x4l);
    cudaGetSymbolAddress((void**)&wah, g_wta_h); cudaGetSymbolAddress((void**)&wal, g_wta_l);
    cudaGetSymbolAddress((void**)&wbh, g_wtb_h); cudaGetSymbolAddress((void**)&wbl, g_wtb_l);
    cudaGetSymbolAddress((void**)&wch, g_wtc_h); cudaGetSymbolAddress((void**)&wcl, g_wtc_l);
    cudaGetSymbolAddress((void**)&wdh, g_wtd_h); cudaGetSymbolAddress((void**)&wdl, g_wtd_l);
    cudaGetSymbolAddress((void**)&part, g_part);

    const int SMEM = 224 * CS * 2 + 2 * 208 * TSN * 2
                   + 4 * 224 * 4 + 256 * 4 + 448 * 4 + 224;
    cudaFuncSetAttribute(prep_gnn, cudaFuncAttributeMaxDynamicSharedMemorySize, SMEM);

    prep_gnn<<<148, 512, SMEM>>>(src, dst, W1, b1, W2, b2, Wa, Wb, Wc, Wd, hgh, hgl);

    // layer a: K=128, no split
    gemm_bf16<<<dim3(8, 16, 1), 256>>>(hgh, hgl, wah, wal, part, 128, 128, 512);
    combine_relu<<<512, 256>>>(part, 1, 512 * 512, ba, x1h, x1l, 512, 512 * 512);
    // layer b: K=512, split 2 -> grid 512
    gemm_bf16<<<dim3(16, 16, 2), 256>>>(x1h, x1l, wbh, wbl, part, 512, 256, 1024);
    combine_relu<<<1024, 256>>>(part, 2, 512 * 1024, bb, x2h, x2l, 1024, 512 * 1024);
    // layer c: K=1024, split 4 -> grid 1024
    gemm_bf16<<<dim3(16, 16, 4), 256>>>(x2h, x2l, wch, wcl, part, 1024, 256, 1024);
    combine_relu<<<1024, 256>>>(part, 4, 512 * 1024, bc, x3h, x3l, 1024, 512 * 1024);
    // layer d: K=1024, split 4 -> grid 512
    gemm_bf16<<<dim3(8, 16, 4), 256>>>(x3h, x3l, wdh, wdl, part, 1024, 256, 512);
    combine_relu<<<512, 256>>>(part, 4, 512 * 512, bd, x4h, x4l, 512, 512 * 512);

    head_softmax<<<64, 256>>>(x4h, x4l, We, be, out);
}

// round 13
// speedup vs baseline: 1.0233x; 1.0134x over previous
#include <cuda_runtime.h>
#include <cuda_bf16.h>

#define NG      512
#define NODES   200
#define EDGES   6400
#define HID     128

typedef __nv_bfloat16 bf16;

// ---- activation buffers (bf16 hi/lo pairs) --------------------------------
__device__ bf16 g_hgh[NG * HID],  g_hgl[NG * HID];
__device__ bf16 g_x1h[NG * 512],  g_x1l[NG * 512];
__device__ bf16 g_x2h[NG * 1024], g_x2l[NG * 1024];
__device__ bf16 g_x3h[NG * 1024], g_x3l[NG * 1024];

// ---- pre-converted transposed weights [N][K] bf16 hi/lo -------------------
__device__ bf16 g_wta_h[512 * 128],   g_wta_l[512 * 128];
__device__ bf16 g_wtb_h[1024 * 512],  g_wtb_l[1024 * 512];
__device__ bf16 g_wtc_h[1024 * 1024], g_wtc_l[1024 * 1024];
__device__ bf16 g_wtd_h[512 * 1024],  g_wtd_l[512 * 1024];

// ---- split-K partial scratch (fp32) ----------------------------------------
__device__ float g_part[4 * 512 * 1024];

// ---- PWL tables + readiness flag (reset by head_softmax each launch) ------
__device__ float g_csorted[128];
__device__ float g_alpha[129 * 128];
__device__ float g_beta[129 * 128];
__device__ unsigned g_pwl_flag = 0;

// ---- asm helpers -----------------------------------------------------------
__device__ __forceinline__ void cp16(void* smem, const void* gmem) {
    unsigned sa = (unsigned)__cvta_generic_to_shared(smem);
    asm volatile("cp.async.cg.shared.global [%0], [%1], 16;\n" :: "r"(sa), "l"(gmem));
}
__device__ __forceinline__ void cp_commit() {
    asm volatile("cp.async.commit_group;\n");
}
template <int N>
__device__ __forceinline__ void cp_wait() {
    asm volatile("cp.async.wait_group %0;\n" :: "n"(N));
}
__device__ __forceinline__ void ldsm4(unsigned r[4], const void* p) {
    unsigned a = (unsigned)__cvta_generic_to_shared(p);
    asm volatile("ldmatrix.sync.aligned.m8n8.x4.shared.b16 {%0,%1,%2,%3}, [%4];\n"
                 : "=r"(r[0]), "=r"(r[1]), "=r"(r[2]), "=r"(r[3]) : "r"(a));
}
__device__ __forceinline__ void ldsm4t(unsigned r[4], const void* p) {
    unsigned a = (unsigned)__cvta_generic_to_shared(p);
    asm volatile("ldmatrix.sync.aligned.m8n8.x4.trans.shared.b16 {%0,%1,%2,%3}, [%4];\n"
                 : "=r"(r[0]), "=r"(r[1]), "=r"(r[2]), "=r"(r[3]) : "r"(a));
}
__device__ __forceinline__ void mma_bf16(float c[4], const unsigned a[4],
                                         unsigned b0, unsigned b1) {
    asm volatile(
        "mma.sync.aligned.m16n8k16.row.col.f32.bf16.bf16.f32 "
        "{%0,%1,%2,%3}, {%4,%5,%6,%7}, {%8,%9}, {%0,%1,%2,%3};\n"
        : "+f"(c[0]), "+f"(c[1]), "+f"(c[2]), "+f"(c[3])
        : "r"(a[0]), "r"(a[1]), "r"(a[2]), "r"(a[3]), "r"(b0), "r"(b1));
}

// ===========================================================================
// PWL table builder (bids 0..15, 8 segments each). tid<128 active.
// ===========================================================================
__device__ void pwl_block(int p, unsigned char* smraw,
    const float* __restrict__ W1, const float* __restrict__ b1,
    const float* __restrict__ W2)
{
    float* sW2 = (float*)smraw;            // 16384 floats
    float* sc  = sW2 + 16384;
    float* sw  = sc + 128;
    float* sb  = sw + 128;
    float* ssc = sb + 128;
    int*  sidx = (int*)(ssc + 128);
    const int tid = threadIdx.x;

    for (int i = tid; i < 4096; i += 512)
        ((float4*)sW2)[i] = ((const float4*)W2)[i];
    if (tid < 128) {
        float w = W1[tid], b = b1[tid];
        sw[tid] = w; sb[tid] = b;
        sc[tid] = (w != 0.0f) ? (-b / w) : __int_as_float(0x7f800000);
    }
    __syncthreads();
    if (tid < 128) {
        float c = sc[tid];
        int r = 0;
        for (int j = 0; j < 128; j++) {
            float cj = sc[j];
            if (cj < c || (cj == c && j < tid)) r++;
        }
        sidx[r] = tid;
        ssc[r]  = c;
    }
    __syncthreads();
    if (tid < 128) {
        if (p == 0) g_csorted[tid] = ssc[tid];
        const int j  = tid;
        const int s0 = p * 8;
        float alpha = 0.0f, beta = 0.0f;
        for (int r = 0; r < 128; r++) {
            int k = sidx[r];
            float w = sw[k], b = sb[k];
            float W2kj = sW2[k * 128 + j];
            if (w == 0.0f) { if (b > 0.0f) beta += b * W2kj; continue; }
            bool active = (w > 0.0f) ? (r < s0) : (r >= s0);
            if (active) { alpha = fmaf(w, W2kj, alpha); beta = fmaf(b, W2kj, beta); }
        }
        for (int s = s0; s < s0 + 8; s++) {
            g_alpha[s * 128 + j] = alpha;
            g_beta[s * 128 + j]  = beta;
            int k = sidx[s];
            float w = sw[k], b = sb[k];
            float W2kj = sW2[k * 128 + j];
            float f = (w > 0.0f) ? 1.0f : ((w < 0.0f) ? -1.0f : 0.0f);
            alpha = fmaf(f * w, W2kj, alpha);
            beta  = fmaf(f * b, W2kj, beta);
        }
        if (p == 15) {
            g_alpha[128 * 128 + j] = alpha;
            g_beta[128 * 128 + j]  = beta;
        }
    }
    __syncthreads();
    if (tid == 0) {
        __threadfence();
        atomicAdd(&g_pwl_flag, 1u);
    }
}

// ===========================================================================
// Weight-convert prologue: grid-stride over 2112 32x32 transpose tiles.
// ===========================================================================
__device__ void conv_block(int w, int stride, unsigned char* smraw,
    const float* __restrict__ Wa, const float* __restrict__ Wb,
    const float* __restrict__ Wc, const float* __restrict__ Wd)
{
    float (*tile)[33] = (float(*)[33])smraw;
    const int tid = threadIdx.x;
    const int c = tid & 31, r = tid >> 5;   // r: 0..15

    for (int t = w; t < 2112; t += stride) {
        const float* W; bf16 *Oh, *Ol; int K, N, tl, tn;
        if (t < 64)        { W = Wa; Oh = g_wta_h; Ol = g_wta_l; K = 128;  N = 512;  tl = t;        tn = 16; }
        else if (t < 576)  { W = Wb; Oh = g_wtb_h; Ol = g_wtb_l; K = 512;  N = 1024; tl = t - 64;   tn = 32; }
        else if (t < 1600) { W = Wc; Oh = g_wtc_h; Ol = g_wtc_l; K = 1024; N = 1024; tl = t - 576;  tn = 32; }
        else               { W = Wd; Oh = g_wtd_h; Ol = g_wtd_l; K = 1024; N = 512;  tl = t - 1600; tn = 16; }
        int nb = (tl % tn) * 32, kb = (tl / tn) * 32;
        #pragma unroll
        for (int j = 0; j < 2; j++)
            tile[r + j * 16][c] = W[(size_t)(kb + r + j * 16) * N + nb + c];
        __syncthreads();
        #pragma unroll
        for (int j = 0; j < 2; j++) {
            int n = nb + r + j * 16;
            float v = tile[c][r + j * 16];
            bf16 h = __float2bfloat16(v);
            Oh[(size_t)n * K + kb + c] = h;
            Ol[(size_t)n * K + kb + c] = __float2bfloat16(v - __bfloat162float(h));
        }
        __syncthreads();
    }
}

// ===========================================================================
// Per-graph GNN block (dense count-matrix + tensor-core SpMM).
// SMEM = 216,544 B
// ===========================================================================
#define CS 216
#define TSN 136

__device__ void gnn_block(int g, unsigned char* smraw,
    const int* __restrict__ src, const int* __restrict__ dst,
    const float* __restrict__ b2,
    bf16* __restrict__ hgh, bf16* __restrict__ hgl)
{
    bf16*  C    = (bf16*)smraw;
    bf16*  th   = C + 224 * CS;
    bf16*  tl   = th + 208 * TSN;
    float* s_a  = (float*)(tl + 208 * TSN);
    float* s_ii = s_a + 224;
    float* s_io = s_ii + 224;
    float* s_s  = s_io + 224;
    float* pool = s_s + 224;                 // 256
    float* colp = pool + 256;                // 448
    unsigned char* seg = (unsigned char*)(colp + 448); // 224

    const int tid   = threadIdx.x;
    const int ebase = g * EDGES;
    const int nbase = g * NODES;

    __syncthreads();   // smem handoff from pwl/conv prologue

    // --- 1. zero C fully; zero t pad rows ---
    {
        uint4 z = {0, 0, 0, 0};
        uint4* C4 = (uint4*)C;
        for (int i = tid; i < 224 * CS * 2 / 16; i += 512) C4[i] = z;
        uint4* tp = (uint4*)(th + 200 * TSN);
        uint4* lp = (uint4*)(tl + 200 * TSN);
        for (int i = tid; i < 8 * TSN * 2 / 16; i += 512) { tp[i] = z; lp[i] = z; }
    }
    __syncthreads();

    // --- 2. count matrix via bf16x2 atomics ---
    {
        const bf16 one = __float2bfloat16(1.0f);
        const bf16 zer = __float2bfloat16(0.0f);
        __nv_bfloat162 v10 = __halves2bfloat162(one, zer);
        __nv_bfloat162 v01 = __halves2bfloat162(zer, one);
        __nv_bfloat162* C2 = (__nv_bfloat162*)C;
        for (int e = tid; e < EDGES; e += 512) {
            int sl = src[ebase + e] - nbase;
            int dl = dst[ebase + e] - nbase;
            atomicAdd(&C2[dl * (CS / 2) + (sl >> 1)], (sl & 1) ? v01 : v10);
        }
    }
    __syncthreads();

    // --- 3. row sums (2-way split) ---
    if (tid < 448) {
        int r = tid % 224, half = tid / 224;
        const __nv_bfloat162* row = (const __nv_bfloat162*)C + r * (CS / 2) + half * 54;
        float sum = 0.0f;
        for (int w = 0; w < 54; w++) {
            float2 f = __bfloat1622float2(row[w]);
            sum += f.x + f.y;
        }
        colp[tid] = sum;
    }
    __syncthreads();
    if (tid < 224) {
        float sum = colp[tid] + colp[224 + tid];
        s_a[tid]  = sum;
        s_ii[tid] = rsqrtf(fmaxf(sum, 1.0f));
    }
    __syncthreads();

    // --- 4. col sums (2-way split over rows) ---
    if (tid < 432) {
        int cc = tid % 216, half = tid / 216;
        float sum = 0.0f;
        for (int d = half * 100; d < half * 100 + 100; d++)
            sum += __bfloat162float(C[d * CS + cc]);
        colp[tid] = sum;
    }
    __syncthreads();
    if (tid < CS) {
        float sum = colp[tid] + colp[216 + tid];
        float io = rsqrtf(fmaxf(sum, 1.0f));
        s_io[tid] = io;
        s_s[tid]  = s_a[tid] * io;
    }
    __syncthreads();

    // --- wait for PWL tables ---
    if (tid == 0) {
        unsigned v;
        do {
            asm volatile("ld.global.acquire.gpu.u32 %0, [%1];"
                         : "=r"(v) : "l"(&g_pwl_flag));
            if (v < 16u) __nanosleep(64);
        } while (v < 16u);
    }
    __syncthreads();

    // --- 5. layer-1 matvec (2-way split) + segment search ---
    if (tid < 400) {
        int d = tid % 200, half = tid / 200;
        const __nv_bfloat162* row = (const __nv_bfloat162*)C + d * (CS / 2) + half * 54;
        const float2* ss2 = (const float2*)s_s + half * 54;
        float sum = 0.0f;
        for (int w = 0; w < 54; w++) {
            float2 f = __bfloat1622float2(row[w]);
            float2 s = ss2[w];
            sum = fmaf(f.x, s.x, fmaf(f.y, s.y, sum));
        }
        colp[tid] = sum;
    }
    __syncthreads();
    if (tid < NODES) {
        float a = (colp[tid] + colp[200 + tid]) * s_ii[tid];
        s_a[tid] = a;
        int lo = 0, hi = 128;
        while (lo < hi) {
            int m = (lo + hi) >> 1;
            if (g_csorted[m] < a) lo = m + 1; else hi = m;
        }
        seg[tid] = (unsigned char)lo;
    }
    __syncthreads();

    // --- 6. t hi/lo ---
    for (int idx = tid; idx < NODES * 32; idx += 512) {
        int i = idx >> 5, q = idx & 31;
        float a  = s_a[i];
        float io = s_io[i];
        int   s  = seg[i];
        float4 al = ((const float4*)(g_alpha + s * 128))[q];
        float4 be = ((const float4*)(g_beta  + s * 128))[q];
        float v0 = fmaf(al.x, a, be.x) * io;
        float v1 = fmaf(al.y, a, be.y) * io;
        float v2 = fmaf(al.z, a, be.z) * io;
        float v3 = fmaf(al.w, a, be.w) * io;
        bf16 h0 = __float2bfloat16(v0), h1 = __float2bfloat16(v1);
        bf16 h2 = __float2bfloat16(v2), h3 = __float2bfloat16(v3);
        __nv_bfloat162 hp0 = __halves2bfloat162(h0, h1);
        __nv_bfloat162 hp1 = __halves2bfloat162(h2, h3);
        __nv_bfloat162 lp0 = __halves2bfloat162(
            __float2bfloat16(v0 - __bfloat162float(h0)),
            __float2bfloat16(v1 - __bfloat162float(h1)));
        __nv_bfloat162 lp1 = __halves2bfloat162(
            __float2bfloat16(v2 - __bfloat162float(h2)),
            __float2bfloat16(v3 - __bfloat162float(h3)));
        __nv_bfloat162* dh = (__nv_bfloat162*)(th + i * TSN + q * 4);
        __nv_bfloat162* dl = (__nv_bfloat162*)(tl + i * TSN + q * 4);
        dh[0] = hp0; dh[1] = hp1;
        dl[0] = lp0; dl[1] = lp1;
    }
    __syncthreads();

    // --- 7. MMA: acc = C @ (th + tl) ---
    const int lane = tid & 31;
    const int wid  = tid >> 5;
    const int wm   = wid & 1;
    const int wn   = wid >> 1;

    float c[7][2][4];
    #pragma unroll
    for (int mi = 0; mi < 7; mi++)
        #pragma unroll
        for (int ni = 0; ni < 2; ni++)
            #pragma unroll
            for (int q = 0; q < 4; q++) c[mi][ni][q] = 0.0f;

    const int aRow = wm * 112 + (lane & 15);
    const int aCol = ((lane >> 4) & 1) * 8;
    const int bRow = (lane & 7) + ((lane >> 4) & 1) * 8;
    const int bCol = wn * 16 + ((lane >> 3) & 1) * 8;

    for (int kt = 0; kt < 13; kt++) {
        unsigned bh[4], bl[4], af[7][4];
        const int kr = kt * 16 + bRow;
        ldsm4t(bh, th + kr * TSN + bCol);
        ldsm4t(bl, tl + kr * TSN + bCol);
        #pragma unroll
        for (int mi = 0; mi < 7; mi++)
            ldsm4(af[mi], C + (aRow + mi * 16) * CS + kt * 16 + aCol);
        #pragma unroll
        for (int mi = 0; mi < 7; mi++) mma_bf16(c[mi][0], af[mi], bh[0], bh[2]);
        #pragma unroll
        for (int mi = 0; mi < 7; mi++) mma_bf16(c[mi][1], af[mi], bh[1], bh[3]);
        #pragma unroll
        for (int mi = 0; mi < 7; mi++) mma_bf16(c[mi][0], af[mi], bl[0], bl[2]);
        #pragma unroll
        for (int mi = 0; mi < 7; mi++) mma_bf16(c[mi][1], af[mi], bl[1], bl[3]);
    }

    // --- 8. epilogue: relu + fused pool ---
    {
        const int gg = lane >> 2;
        const int tg = lane & 3;
        float bx[2], by[2];
        #pragma unroll
        for (int ni = 0; ni < 2; ni++) {
            int col = wn * 16 + ni * 8 + tg * 2;
            float2 bv = *(const float2*)(b2 + col);
            bx[ni] = bv.x; by[ni] = bv.y;
        }
        float ps[2][2] = {{0, 0}, {0, 0}};
        #pragma unroll
        for (int mi = 0; mi < 7; mi++) {
            int r0 = wm * 112 + mi * 16 + gg;
            int r1 = r0 + 8;
            float ii0 = (r0 < NODES) ? s_ii[r0] : 0.0f;
            float ii1 = (r1 < NODES) ? s_ii[r1] : 0.0f;
            #pragma unroll
            for (int ni = 0; ni < 2; ni++) {
                if (r0 < NODES) {
                    ps[ni][0] += fmaxf(fmaf(c[mi][ni][0], ii0, bx[ni]), 0.0f);
                    ps[ni][1] += fmaxf(fmaf(c[mi][ni][1], ii0, by[ni]), 0.0f);
                }
                if (r1 < NODES) {
                    ps[ni][0] += fmaxf(fmaf(c[mi][ni][2], ii1, bx[ni]), 0.0f);
                    ps[ni][1] += fmaxf(fmaf(c[mi][ni][3], ii1, by[ni]), 0.0f);
                }
            }
        }
        #pragma unroll
        for (int off = 16; off >= 4; off >>= 1) {
            #pragma unroll
            for (int ni = 0; ni < 2; ni++) {
                ps[ni][0] += __shfl_down_sync(0xffffffffu, ps[ni][0], off);
                ps[ni][1] += __shfl_down_sync(0xffffffffu, ps[ni][1], off);
            }
        }
        if (lane < 4) {
            #pragma unroll
            for (int ni = 0; ni < 2; ni++) {
                int col = wn * 16 + ni * 8 + lane * 2;
                pool[wm * 128 + col]     = ps[ni][0];
                pool[wm * 128 + col + 1] = ps[ni][1];
            }
        }
    }
    __syncthreads();
    if (tid < HID) {
        float v = (pool[tid] + pool[128 + tid]) * (1.0f / 200.0f);
        bf16 h = __float2bfloat16(v);
        hgh[g * HID + tid] = h;
        hgl[g * HID + tid] = __float2bfloat16(v - __bfloat162float(h));
    }
}

// ===========================================================================
// Merged kernel (R9 form): 512 CTAs x 512 threads. bid<16: pwl; else conv
// prologue; all: gnn for graph bid.
// ===========================================================================
__global__ void __launch_bounds__(512, 1) prep_gnn(
    const int* __restrict__ src, const int* __restrict__ dst,
    const float* __restrict__ W1, const float* __restrict__ b1,
    const float* __restrict__ W2, const float* __restrict__ b2,
    const float* __restrict__ Wa, const float* __restrict__ Wb,
    const float* __restrict__ Wc, const float* __restrict__ Wd,
    bf16* __restrict__ hgh, bf16* __restrict__ hgl)
{
    extern __shared__ unsigned char smraw[];
    const int bid = blockIdx.x;
    if (bid < 16) pwl_block(bid, smraw, W1, b1, W2);
    else          conv_block(bid - 16, 496, smraw, Wa, Wb, Wc, Wd);
    gnn_block(bid, smraw, src, dst, b2, hgh, hgl);
}

// ---------------------------------------------------------------------------
// Split-K bf16 hi/lo tensor-core GEMM: 32x64 tile, 256 threads, 2-stage
// pipeline. If bias != nullptr (single chunk), fused bias+relu+bf16 hi/lo
// epilogue to Oh/Ol; else fp32 partials to part[z].
// ---------------------------------------------------------------------------
#define TSB 40

__global__ void __launch_bounds__(256) gemm_bf16(
    const bf16* __restrict__ Ah, const bf16* __restrict__ Al,
    const bf16* __restrict__ Bh, const bf16* __restrict__ Bl,
    float* __restrict__ part,
    const float* __restrict__ bias,
    bf16* __restrict__ Oh, bf16* __restrict__ Ol,
    int Ktot, int Kchunk, int Nc)
{
    __shared__ bf16 sAh[2][32 * TSB], sAl[2][32 * TSB];
    __shared__ bf16 sBh[2][64 * TSB], sBl[2][64 * TSB];

    const int tid  = threadIdx.x;
    const int lane = tid & 31;
    const int wid  = tid >> 5;
    const int wm   = wid & 1;           // 2 m-groups x 16 rows
    const int wn   = wid >> 1;          // 4 n-groups x 16 cols
    const int row0 = blockIdx.y * 32, col0 = blockIdx.x * 64;
    const int z    = blockIdx.z;
    const int kofs = z * Kchunk;

    const int th  = tid & 127;
    const int lr  = th >> 2;            // 0..31
    const int lc  = (th & 3) * 8;
    const bool pl = (tid < 128);

    const bf16* gA  = (pl ? Ah : Al) + (size_t)(row0 + lr) * Ktot + kofs + lc;
    const bf16* gB0 = (pl ? Bh : Bl) + (size_t)(col0 + lr) * Ktot + kofs + lc;
    const bf16* gB1 = (pl ? Bh : Bl) + (size_t)(col0 + 32 + lr) * Ktot + kofs + lc;
    bf16* dA0 = (pl ? sAh[0] : sAl[0]) + lr * TSB + lc;
    bf16* dB0 = (pl ? sBh[0] : sBl[0]) + lr * TSB + lc;
    bf16* dA1 = (pl ? sAh[1] : sAl[1]) + lr * TSB + lc;
    bf16* dB1 = (pl ? sBh[1] : sBl[1]) + lr * TSB + lc;

    float c[2][4];
    #pragma unroll
    for (int ni = 0; ni < 2; ni++)
        #pragma unroll
        for (int q = 0; q < 4; q++) c[ni][q] = 0.0f;

    cp16(dA0, gA);
    cp16(dB0, gB0);
    cp16(dB0 + 32 * TSB, gB1);
    cp_commit();

    const int nkt = Kchunk >> 5;
    const int frow = lane & 15;
    const int fk   = (lane >> 4) * 8;
    int buf = 0;

    for (int kt = 0; kt < nkt; kt++) {
        if (kt + 1 < nkt) {
            bf16* dA = buf ? dA0 : dA1;
            bf16* dB = buf ? dB0 : dB1;
            cp16(dA, gA + (size_t)(kt + 1) * 32);
            cp16(dB, gB0 + (size_t)(kt + 1) * 32);
            cp16(dB + 32 * TSB, gB1 + (size_t)(kt + 1) * 32);
            cp_commit();
            cp_wait<1>();
        } else {
            cp_wait<0>();
        }
        __syncthreads();

        #pragma unroll
        for (int ks = 0; ks < 32; ks += 16) {
            unsigned ah[4], al[4], bh[4], bl[4];
            {
                int ro = (wm * 16 + frow) * TSB + ks + fk;
                ldsm4(ah, &sAh[buf][ro]);
                ldsm4(al, &sAl[buf][ro]);
            }
            {
                int no = (wn * 16 + frow) * TSB + ks + fk;
                ldsm4(bh, &sBh[buf][no]);
                ldsm4(bl, &sBl[buf][no]);
            }
            mma_bf16(c[0], ah, bh[0], bh[2]);
            mma_bf16(c[1], ah, bh[1], bh[3]);
            mma_bf16(c[0], ah, bl[0], bl[2]);
            mma_bf16(c[1], ah, bl[1], bl[3]);
            mma_bf16(c[0], al, bh[0], bh[2]);
            mma_bf16(c[1], al, bh[1], bh[3]);
        }
        __syncthreads();
        buf ^= 1;
    }

    const int g  = lane >> 2;
    const int tg = lane & 3;
    if (bias) {
        // fused epilogue (single-chunk layers)
        #pragma unroll
        for (int ni = 0; ni < 2; ni++) {
            int r  = row0 + wm * 16 + g;
            int cc = col0 + wn * 16 + ni * 8 + tg * 2;
            float2 bv = *(const float2*)(bias + cc);
            #pragma unroll
            for (int half = 0; half < 2; half++) {
                int rr = r + half * 8;
                float vx = fmaxf(c[ni][half * 2 + 0] + bv.x, 0.0f);
                float vy = fmaxf(c[ni][half * 2 + 1] + bv.y, 0.0f);
                bf16 hx = __float2bfloat16(vx);
                bf16 hy = __float2bfloat16(vy);
                *(__nv_bfloat162*)(Oh + (size_t)rr * Nc + cc) =
                    __halves2bfloat162(hx, hy);
                *(__nv_bfloat162*)(Ol + (size_t)rr * Nc + cc) =
                    __halves2bfloat162(
                        __float2bfloat16(vx - __bfloat162float(hx)),
                        __float2bfloat16(vy - __bfloat162float(hy)));
            }
        }
    } else {
        float* po = part + (size_t)z * 512 * Nc;
        #pragma unroll
        for (int ni = 0; ni < 2; ni++) {
            int r  = row0 + wm * 16 + g;
            int cc = col0 + wn * 16 + ni * 8 + tg * 2;
            *(float2*)(po + (size_t)r * Nc + cc)       = make_float2(c[ni][0], c[ni][1]);
            *(float2*)(po + (size_t)(r + 8) * Nc + cc) = make_float2(c[ni][2], c[ni][3]);
        }
    }
}

// ---------------------------------------------------------------------------
// Combine split-K partials: out = relu(sum_s part[s] + bias) -> bf16 hi/lo.
// ---------------------------------------------------------------------------
__global__ void __launch_bounds__(256) combine_relu(
    const float* __restrict__ part, int S, int zstride,
    const float* __restrict__ bias,
    bf16* __restrict__ Oh, bf16* __restrict__ Ol,
    int Nc, int total)
{
    int i2 = (blockIdx.x * 256 + threadIdx.x) * 2;
    if (i2 >= total) return;
    float2 s = *(const float2*)(part + i2);
    for (int z = 1; z < S; z++) {
        float2 p = *(const float2*)(part + (size_t)z * zstride + i2);
        s.x += p.x; s.y += p.y;
    }
    int col = i2 % Nc;
    float2 bv = *(const float2*)(bias + col);
    float vx = fmaxf(s.x + bv.x, 0.0f);
    float vy = fmaxf(s.y + bv.y, 0.0f);
    bf16 hx = __float2bfloat16(vx);
    bf16 hy = __float2bfloat16(vy);
    *(__nv_bfloat162*)(Oh + i2) = __halves2bfloat162(hx, hy);
    *(__nv_bfloat162*)(Ol + i2) = __halves2bfloat162(
        __float2bfloat16(vx - __bfloat162float(hx)),
        __float2bfloat16(vy - __bfloat162float(hy)));
}

// ---------------------------------------------------------------------------
// Final layer: reads layer-d fp32 partials directly (sum + bd + relu inline),
// computes softmax head. Also resets cross-kernel flags for next replay.
// ---------------------------------------------------------------------------
__global__ void __launch_bounds__(256) head_softmax(
    const float* __restrict__ part,   // 4 x [512 x 512] fp32 partials
    const float* __restrict__ bd,
    const float* __restrict__ We, const float* __restrict__ be,
    float* __restrict__ out)
{
    if (blockIdx.x == 0 && threadIdx.x == 0) g_pwl_flag = 0;

    __shared__ float Ws[512 * 10];
    const int tid = threadIdx.x;
    for (int i = tid; i < 512 * 10; i += 256) Ws[i] = We[i];
    __syncthreads();
    const int lane = tid & 31, w = tid >> 5;
    const int row = blockIdx.x * 8 + w;
    const size_t D = 512 * 512;
    const float* p0 = part + (size_t)row * 512;

    float acc[10];
    #pragma unroll
    for (int c = 0; c < 10; c++) acc[c] = 0.0f;
    for (int k = lane; k < 512; k += 32) {
        float s = p0[k] + p0[k + D] + p0[k + 2 * D] + p0[k + 3 * D];
        float a = fmaxf(s + bd[k], 0.0f);
        #pragma unroll
        for (int c = 0; c < 10; c++) acc[c] = fmaf(a, Ws[k * 10 + c], acc[c]);
    }
    #pragma unroll
    for (int c = 0; c < 10; c++) {
        #pragma unroll
        for (int o = 16; o > 0; o >>= 1)
            acc[c] += __shfl_xor_sync(0xffffffffu, acc[c], o);
    }
    if (lane == 0) {
        float v[10], mx = -1e30f;
        #pragma unroll
        for (int c = 0; c < 10; c++) { v[c] = acc[c] + be[c]; mx = fmaxf(mx, v[c]); }
        float s = 0.0f;
        #pragma unroll
        for (int c = 0; c < 10; c++) { v[c] = __expf(v[c] - mx); s += v[c]; }
        float inv = 1.0f / s;
        #pragma unroll
        for (int c = 0; c < 10; c++) out[row * 10 + c] = v[c] * inv;
    }
}

// ---------------------------------------------------------------------------
extern "C" void kernel_launch(void* const* d_in, const int* in_sizes, int n_in,
                              void* d_out, int out_size)
{
    const int*   src = (const int*)  d_in[0];
    const int*   dst = (const int*)  d_in[1];
    const float* W1  = (const float*)d_in[2];
    const float* b1  = (const float*)d_in[3];
    const float* W2  = (const float*)d_in[4];
    const float* b2  = (const float*)d_in[5];
    const float* Wa  = (const float*)d_in[6];
    const float* ba  = (const float*)d_in[7];
    const float* Wb  = (const float*)d_in[8];
    const float* bb  = (const float*)d_in[9];
    const float* Wc  = (const float*)d_in[10];
    const float* bc  = (const float*)d_in[11];
    const float* Wd  = (const float*)d_in[12];
    const float* bd  = (const float*)d_in[13];
    const float* We  = (const float*)d_in[14];
    const float* be  = (const float*)d_in[15];
    float* out = (float*)d_out;

    bf16 *hgh, *hgl, *x1h, *x1l, *x2h, *x2l, *x3h, *x3l;
    bf16 *wah, *wal, *wbh, *wbl, *wch, *wcl, *wdh, *wdl;
    float* part;
    cudaGetSymbolAddress((void**)&hgh, g_hgh); cudaGetSymbolAddress((void**)&hgl, g_hgl);
    cudaGetSymbolAddress((void**)&x1h, g_x1h); cudaGetSymbolAddress((void**)&x1l, g_x1l);
    cudaGetSymbolAddress((void**)&x2h, g_x2h); cudaGetSymbolAddress((void**)&x2l, g_x2l);
    cudaGetSymbolAddress((void**)&x3h, g_x3h); cudaGetSymbolAddress((void**)&x3l, g_x3l);
    cudaGetSymbolAddress((void**)&wah, g_wta_h); cudaGetSymbolAddress((void**)&wal, g_wta_l);
    cudaGetSymbolAddress((void**)&wbh, g_wtb_h); cudaGetSymbolAddress((void**)&wbl, g_wtb_l);
    cudaGetSymbolAddress((void**)&wch, g_wtc_h); cudaGetSymbolAddress((void**)&wcl, g_wtc_l);
    cudaGetSymbolAddress((void**)&wdh, g_wtd_h); cudaGetSymbolAddress((void**)&wdl, g_wtd_l);
    cudaGetSymbolAddress((void**)&part, g_part);

    const int SMEM = 224 * CS * 2 + 2 * 208 * TSN * 2
                   + 4 * 224 * 4 + 256 * 4 + 448 * 4 + 224;
    cudaFuncSetAttribute(prep_gnn, cudaFuncAttributeMaxDynamicSharedMemorySize, SMEM);

    prep_gnn<<<512, 512, SMEM>>>(src, dst, W1, b1, W2, b2, Wa, Wb, Wc, Wd, hgh, hgl);

    // layer a: K=128, single chunk, fused epilogue
    gemm_bf16<<<dim3(8, 16, 1), 256>>>(hgh, hgl, wah, wal, nullptr, ba,
                                       x1h, x1l, 128, 128, 512);
    // layer b: K=512, split 2 -> grid 512
    gemm_bf16<<<dim3(16, 16, 2), 256>>>(x1h, x1l, wbh, wbl, part, nullptr,
                                        nullptr, nullptr, 512, 256, 1024);
    combine_relu<<<1024, 256>>>(part, 2, 512 * 1024, bb, x2h, x2l, 1024, 512 * 1024);
    // layer c: K=1024, split 4 -> grid 1024
    gemm_bf16<<<dim3(16, 16, 4), 256>>>(x2h, x2l, wch, wcl, part, nullptr,
                                        nullptr, nullptr, 1024, 256, 1024);
    combine_relu<<<1024, 256>>>(part, 4, 512 * 1024, bc, x3h, x3l, 1024, 512 * 1024);
    // layer d: K=1024, split 4 -> grid 512, partials consumed by head
    gemm_bf16<<<dim3(8, 16, 4), 256>>>(x3h, x3l, wdh, wdl, part, nullptr,
                                       nullptr, nullptr, 1024, 256, 512);

    head_softmax<<<64, 256>>>(part, bd, We, be, out);
}

// round 14
// speedup vs baseline: 1.0376x; 1.0141x over previous
#include <cuda_runtime.h>
#include <cuda_bf16.h>

#define NG      512
#define NODES   200
#define EDGES   6400
#define HID     128

typedef __nv_bfloat16 bf16;

// ---- activation buffers (bf16 hi/lo pairs) --------------------------------
__device__ bf16 g_hgh[NG * HID],  g_hgl[NG * HID];
__device__ bf16 g_x1h[NG * 512],  g_x1l[NG * 512];
__device__ bf16 g_x2h[NG * 1024], g_x2l[NG * 1024];
__device__ bf16 g_x3h[NG * 1024], g_x3l[NG * 1024];

// ---- pre-converted transposed weights [N][K] bf16 hi/lo -------------------
__device__ bf16 g_wta_h[512 * 128],   g_wta_l[512 * 128];
__device__ bf16 g_wtb_h[1024 * 512],  g_wtb_l[1024 * 512];
__device__ bf16 g_wtc_h[1024 * 1024], g_wtc_l[1024 * 1024];
__device__ bf16 g_wtd_h[512 * 1024],  g_wtd_l[512 * 1024];

// ---- split-K partial scratch (fp32) ----------------------------------------
__device__ float g_part[4 * 512 * 1024];

// ---- PWL tables + readiness flag (reset by head_softmax each launch) ------
__device__ float g_csorted[128];
__device__ float g_alpha[129 * 128];
__device__ float g_beta[129 * 128];
__device__ unsigned g_pwl_flag = 0;

// ---- asm helpers -----------------------------------------------------------
__device__ __forceinline__ void cp16(void* smem, const void* gmem) {
    unsigned sa = (unsigned)__cvta_generic_to_shared(smem);
    asm volatile("cp.async.cg.shared.global [%0], [%1], 16;\n" :: "r"(sa), "l"(gmem));
}
__device__ __forceinline__ void cp_commit() {
    asm volatile("cp.async.commit_group;\n");
}
template <int N>
__device__ __forceinline__ void cp_wait() {
    asm volatile("cp.async.wait_group %0;\n" :: "n"(N));
}
__device__ __forceinline__ void ldsm4(unsigned r[4], const void* p) {
    unsigned a = (unsigned)__cvta_generic_to_shared(p);
    asm volatile("ldmatrix.sync.aligned.m8n8.x4.shared.b16 {%0,%1,%2,%3}, [%4];\n"
                 : "=r"(r[0]), "=r"(r[1]), "=r"(r[2]), "=r"(r[3]) : "r"(a));
}
__device__ __forceinline__ void ldsm4t(unsigned r[4], const void* p) {
    unsigned a = (unsigned)__cvta_generic_to_shared(p);
    asm volatile("ldmatrix.sync.aligned.m8n8.x4.trans.shared.b16 {%0,%1,%2,%3}, [%4];\n"
                 : "=r"(r[0]), "=r"(r[1]), "=r"(r[2]), "=r"(r[3]) : "r"(a));
}
__device__ __forceinline__ void mma_bf16(float c[4], const unsigned a[4],
                                         unsigned b0, unsigned b1) {
    asm volatile(
        "mma.sync.aligned.m16n8k16.row.col.f32.bf16.bf16.f32 "
        "{%0,%1,%2,%3}, {%4,%5,%6,%7}, {%8,%9}, {%0,%1,%2,%3};\n"
        : "+f"(c[0]), "+f"(c[1]), "+f"(c[2]), "+f"(c[3])
        : "r"(a[0]), "r"(a[1]), "r"(a[2]), "r"(a[3]), "r"(b0), "r"(b1));
}

// ===========================================================================
// PWL table builder (bids 0..15, 8 segments each). tid<128 active.
// ===========================================================================
__device__ void pwl_block(int p, unsigned char* smraw,
    const float* __restrict__ W1, const float* __restrict__ b1,
    const float* __restrict__ W2)
{
    float* sW2 = (float*)smraw;            // 16384 floats
    float* sc  = sW2 + 16384;
    float* sw  = sc + 128;
    float* sb  = sw + 128;
    float* ssc = sb + 128;
    int*  sidx = (int*)(ssc + 128);
    const int tid = threadIdx.x;

    for (int i = tid; i < 4096; i += 512)
        ((float4*)sW2)[i] = ((const float4*)W2)[i];
    if (tid < 128) {
        float w = W1[tid], b = b1[tid];
        sw[tid] = w; sb[tid] = b;
        sc[tid] = (w != 0.0f) ? (-b / w) : __int_as_float(0x7f800000);
    }
    __syncthreads();
    if (tid < 128) {
        float c = sc[tid];
        int r = 0;
        for (int j = 0; j < 128; j++) {
            float cj = sc[j];
            if (cj < c || (cj == c && j < tid)) r++;
        }
        sidx[r] = tid;
        ssc[r]  = c;
    }
    __syncthreads();
    if (tid < 128) {
        if (p == 0) g_csorted[tid] = ssc[tid];
        const int j  = tid;
        const int s0 = p * 8;
        float alpha = 0.0f, beta = 0.0f;
        for (int r = 0; r < 128; r++) {
            int k = sidx[r];
            float w = sw[k], b = sb[k];
            float W2kj = sW2[k * 128 + j];
            if (w == 0.0f) { if (b > 0.0f) beta += b * W2kj; continue; }
            bool active = (w > 0.0f) ? (r < s0) : (r >= s0);
            if (active) { alpha = fmaf(w, W2kj, alpha); beta = fmaf(b, W2kj, beta); }
        }
        for (int s = s0; s < s0 + 8; s++) {
            g_alpha[s * 128 + j] = alpha;
            g_beta[s * 128 + j]  = beta;
            int k = sidx[s];
            float w = sw[k], b = sb[k];
            float W2kj = sW2[k * 128 + j];
            float f = (w > 0.0f) ? 1.0f : ((w < 0.0f) ? -1.0f : 0.0f);
            alpha = fmaf(f * w, W2kj, alpha);
            beta  = fmaf(f * b, W2kj, beta);
        }
        if (p == 15) {
            g_alpha[128 * 128 + j] = alpha;
            g_beta[128 * 128 + j]  = beta;
        }
    }
    __syncthreads();
    if (tid == 0) {
        __threadfence();
        atomicAdd(&g_pwl_flag, 1u);
    }
}

// ===========================================================================
// Weight-convert prologue: grid-stride over 2112 32x32 transpose tiles.
// ===========================================================================
__device__ void conv_block(int w, int stride, unsigned char* smraw,
    const float* __restrict__ Wa, const float* __restrict__ Wb,
    const float* __restrict__ Wc, const float* __restrict__ Wd)
{
    float (*tile)[33] = (float(*)[33])smraw;
    const int tid = threadIdx.x;
    const int c = tid & 31, r = tid >> 5;   // r: 0..15

    for (int t = w; t < 2112; t += stride) {
        const float* W; bf16 *Oh, *Ol; int K, N, tl, tn;
        if (t < 64)        { W = Wa; Oh = g_wta_h; Ol = g_wta_l; K = 128;  N = 512;  tl = t;        tn = 16; }
        else if (t < 576)  { W = Wb; Oh = g_wtb_h; Ol = g_wtb_l; K = 512;  N = 1024; tl = t - 64;   tn = 32; }
        else if (t < 1600) { W = Wc; Oh = g_wtc_h; Ol = g_wtc_l; K = 1024; N = 1024; tl = t - 576;  tn = 32; }
        else               { W = Wd; Oh = g_wtd_h; Ol = g_wtd_l; K = 1024; N = 512;  tl = t - 1600; tn = 16; }
        int nb = (tl % tn) * 32, kb = (tl / tn) * 32;
        #pragma unroll
        for (int j = 0; j < 2; j++)
            tile[r + j * 16][c] = W[(size_t)(kb + r + j * 16) * N + nb + c];
        __syncthreads();
        #pragma unroll
        for (int j = 0; j < 2; j++) {
            int n = nb + r + j * 16;
            float v = tile[c][r + j * 16];
            bf16 h = __float2bfloat16(v);
            Oh[(size_t)n * K + kb + c] = h;
            Ol[(size_t)n * K + kb + c] = __float2bfloat16(v - __bfloat162float(h));
        }
        __syncthreads();
    }
}

// ===========================================================================
// Per-graph GNN block (dense count-matrix + tensor-core SpMM).
// Count build: native u32 atomics on a 4-bit-packed array overlaid on the
// tail of the bf16 C buffer (bytes [75168, 96768)), then expansion to bf16.
// SMEM = 216,544 B
// ===========================================================================
#define CS 216
#define TSN 136
#define U4OFF_W 18792            // u32 word offset of u4 area (byte 75168)
#define U4ROWW  27               // u32 words per row (216/8)

__device__ void gnn_block(int g, unsigned char* smraw,
    const int* __restrict__ src, const int* __restrict__ dst,
    const float* __restrict__ b2,
    bf16* __restrict__ hgh, bf16* __restrict__ hgl)
{
    bf16*  C    = (bf16*)smraw;
    bf16*  th   = C + 224 * CS;
    bf16*  tl   = th + 208 * TSN;
    float* s_a  = (float*)(tl + 208 * TSN);
    float* s_ii = s_a + 224;
    float* s_io = s_ii + 224;
    float* s_s  = s_io + 224;
    float* pool = s_s + 224;                 // 256
    float* colp = pool + 256;                // 448
    unsigned char* seg = (unsigned char*)(colp + 448); // 224
    unsigned* Cu = (unsigned*)C + U4OFF_W;   // u4-packed counts [200][27]

    const int tid   = threadIdx.x;
    const int ebase = g * EDGES;
    const int nbase = g * NODES;

    __syncthreads();   // smem handoff from pwl/conv prologue

    // --- 1. zero u4 count area (21600 B) + t pad rows ---
    {
        uint4 z = {0, 0, 0, 0};
        uint4* u4a = (uint4*)Cu;             // 1350 uint4
        for (int i = tid; i < 1350; i += 512) u4a[i] = z;
        uint4* tp = (uint4*)(th + 200 * TSN);
        uint4* lp = (uint4*)(tl + 200 * TSN);
        for (int i = tid; i < 8 * TSN * 2 / 16; i += 512) { tp[i] = z; lp[i] = z; }
    }
    __syncthreads();

    // --- 2. count matrix: one native u32 atomic per edge (4-bit cells) ---
    for (int e = tid; e < EDGES; e += 512) {
        int sl = src[ebase + e] - nbase;
        int dl = dst[ebase + e] - nbase;
        atomicAdd(&Cu[dl * U4ROWW + (sl >> 3)], 1u << (4 * (sl & 7)));
    }
    __syncthreads();

    // --- 2b. expand u4 -> bf16, phase A: rows 0..173 (writes < byte 75168) ---
    for (int t = tid; t < 174 * U4ROWW; t += 512) {
        int d = t / U4ROWW, w = t % U4ROWW;
        unsigned word = Cu[d * U4ROWW + w];
        __nv_bfloat162* o = (__nv_bfloat162*)(C + d * CS + w * 8);
        #pragma unroll
        for (int q = 0; q < 4; q++) {
            float v0 = (float)((word >> (8 * q))     & 15u);
            float v1 = (float)((word >> (8 * q + 4)) & 15u);
            o[q] = __halves2bfloat162(__float2bfloat16(v0), __float2bfloat16(v1));
        }
    }
    __syncthreads();
    // --- 2c. phase B: rows 174..199 (reads [93960,96768), writes [75168,86400))
    for (int t = tid; t < 26 * U4ROWW; t += 512) {
        int d = 174 + t / U4ROWW, w = t % U4ROWW;
        unsigned word = Cu[d * U4ROWW + w];
        __nv_bfloat162* o = (__nv_bfloat162*)(C + d * CS + w * 8);
        #pragma unroll
        for (int q = 0; q < 4; q++) {
            float v0 = (float)((word >> (8 * q))     & 15u);
            float v1 = (float)((word >> (8 * q + 4)) & 15u);
            o[q] = __halves2bfloat162(__float2bfloat16(v0), __float2bfloat16(v1));
        }
    }
    __syncthreads();
    // --- 2d. re-zero pad rows 200..223 (bytes [86400,96768), stale u4 data) ---
    {
        uint4 z = {0, 0, 0, 0};
        uint4* pz = (uint4*)((unsigned char*)C + 86400);   // 648 uint4
        for (int i = tid; i < 648; i += 512) pz[i] = z;
    }
    __syncthreads();

    // --- 3. row sums (2-way split) ---
    if (tid < 448) {
        int r = tid % 224, half = tid / 224;
        const __nv_bfloat162* row = (const __nv_bfloat162*)C + r * (CS / 2) + half * 54;
        float sum = 0.0f;
        for (int w = 0; w < 54; w++) {
            float2 f = __bfloat1622float2(row[w]);
            sum += f.x + f.y;
        }
        colp[tid] = sum;
    }
    __syncthreads();
    if (tid < 224) {
        float sum = colp[tid] + colp[224 + tid];
        s_a[tid]  = sum;
        s_ii[tid] = rsqrtf(fmaxf(sum, 1.0f));
    }
    __syncthreads();

    // --- 4. col sums (2-way split over rows) ---
    if (tid < 432) {
        int cc = tid % 216, half = tid / 216;
        float sum = 0.0f;
        for (int d = half * 100; d < half * 100 + 100; d++)
            sum += __bfloat162float(C[d * CS + cc]);
        colp[tid] = sum;
    }
    __syncthreads();
    if (tid < CS) {
        float sum = colp[tid] + colp[216 + tid];
        float io = rsqrtf(fmaxf(sum, 1.0f));
        s_io[tid] = io;
        s_s[tid]  = s_a[tid] * io;
    }
    __syncthreads();

    // --- wait for PWL tables ---
    if (tid == 0) {
        unsigned v;
        do {
            asm volatile("ld.global.acquire.gpu.u32 %0, [%1];"
                         : "=r"(v) : "l"(&g_pwl_flag));
            if (v < 16u) __nanosleep(64);
        } while (v < 16u);
    }
    __syncthreads();

    // --- 5. layer-1 matvec (2-way split) + segment search ---
    if (tid < 400) {
        int d = tid % 200, half = tid / 200;
        const __nv_bfloat162* row = (const __nv_bfloat162*)C + d * (CS / 2) + half * 54;
        const float2* ss2 = (const float2*)s_s + half * 54;
        float sum = 0.0f;
        for (int w = 0; w < 54; w++) {
            float2 f = __bfloat1622float2(row[w]);
            float2 s = ss2[w];
            sum = fmaf(f.x, s.x, fmaf(f.y, s.y, sum));
        }
        colp[tid] = sum;
    }
    __syncthreads();
    if (tid < NODES) {
        float a = (colp[tid] + colp[200 + tid]) * s_ii[tid];
        s_a[tid] = a;
        int lo = 0, hi = 128;
        while (lo < hi) {
            int m = (lo + hi) >> 1;
            if (g_csorted[m] < a) lo = m + 1; else hi = m;
        }
        seg[tid] = (unsigned char)lo;
    }
    __syncthreads();

    // --- 6. t hi/lo ---
    for (int idx = tid; idx < NODES * 32; idx += 512) {
        int i = idx >> 5, q = idx & 31;
        float a  = s_a[i];
        float io = s_io[i];
        int   s  = seg[i];
        float4 al = ((const float4*)(g_alpha + s * 128))[q];
        float4 be = ((const float4*)(g_beta  + s * 128))[q];
        float v0 = fmaf(al.x, a, be.x) * io;
        float v1 = fmaf(al.y, a, be.y) * io;
        float v2 = fmaf(al.z, a, be.z) * io;
        float v3 = fmaf(al.w, a, be.w) * io;
        bf16 h0 = __float2bfloat16(v0), h1 = __float2bfloat16(v1);
        bf16 h2 = __float2bfloat16(v2), h3 = __float2bfloat16(v3);
        __nv_bfloat162 hp0 = __halves2bfloat162(h0, h1);
        __nv_bfloat162 hp1 = __halves2bfloat162(h2, h3);
        __nv_bfloat162 lp0 = __halves2bfloat162(
            __float2bfloat16(v0 - __bfloat162float(h0)),
            __float2bfloat16(v1 - __bfloat162float(h1)));
        __nv_bfloat162 lp1 = __halves2bfloat162(
            __float2bfloat16(v2 - __bfloat162float(h2)),
            __float2bfloat16(v3 - __bfloat162float(h3)));
        __nv_bfloat162* dh = (__nv_bfloat162*)(th + i * TSN + q * 4);
        __nv_bfloat162* dl = (__nv_bfloat162*)(tl + i * TSN + q * 4);
        dh[0] = hp0; dh[1] = hp1;
        dl[0] = lp0; dl[1] = lp1;
    }
    __syncthreads();

    // --- 7. MMA: acc = C @ (th + tl) ---
    const int lane = tid & 31;
    const int wid  = tid >> 5;
    const int wm   = wid & 1;
    const int wn   = wid >> 1;

    float c[7][2][4];
    #pragma unroll
    for (int mi = 0; mi < 7; mi++)
        #pragma unroll
        for (int ni = 0; ni < 2; ni++)
            #pragma unroll
            for (int q = 0; q < 4; q++) c[mi][ni][q] = 0.0f;

    const int aRow = wm * 112 + (lane & 15);
    const int aCol = ((lane >> 4) & 1) * 8;
    const int bRow = (lane & 7) + ((lane >> 4) & 1) * 8;
    const int bCol = wn * 16 + ((lane >> 3) & 1) * 8;

    for (int kt = 0; kt < 13; kt++) {
        unsigned bh[4], bl[4], af[7][4];
        const int kr = kt * 16 + bRow;
        ldsm4t(bh, th + kr * TSN + bCol);
        ldsm4t(bl, tl + kr * TSN + bCol);
        #pragma unroll
        for (int mi = 0; mi < 7; mi++)
            ldsm4(af[mi], C + (aRow + mi * 16) * CS + kt * 16 + aCol);
        #pragma unroll
        for (int mi = 0; mi < 7; mi++) mma_bf16(c[mi][0], af[mi], bh[0], bh[2]);
        #pragma unroll
        for (int mi = 0; mi < 7; mi++) mma_bf16(c[mi][1], af[mi], bh[1], bh[3]);
        #pragma unroll
        for (int mi = 0; mi < 7; mi++) mma_bf16(c[mi][0], af[mi], bl[0], bl[2]);
        #pragma unroll
        for (int mi = 0; mi < 7; mi++) mma_bf16(c[mi][1], af[mi], bl[1], bl[3]);
    }

    // --- 8. epilogue: relu + fused pool ---
    {
        const int gg = lane >> 2;
        const int tg = lane & 3;
        float bx[2], by[2];
        #pragma unroll
        for (int ni = 0; ni < 2; ni++) {
            int col = wn * 16 + ni * 8 + tg * 2;
            float2 bv = *(const float2*)(b2 + col);
            bx[ni] = bv.x; by[ni] = bv.y;
        }
        float ps[2][2] = {{0, 0}, {0, 0}};
        #pragma unroll
        for (int mi = 0; mi < 7; mi++) {
            int r0 = wm * 112 + mi * 16 + gg;
            int r1 = r0 + 8;
            float ii0 = (r0 < NODES) ? s_ii[r0] : 0.0f;
            float ii1 = (r1 < NODES) ? s_ii[r1] : 0.0f;
            #pragma unroll
            for (int ni = 0; ni < 2; ni++) {
                if (r0 < NODES) {
                    ps[ni][0] += fmaxf(fmaf(c[mi][ni][0], ii0, bx[ni]), 0.0f);
                    ps[ni][1] += fmaxf(fmaf(c[mi][ni][1], ii0, by[ni]), 0.0f);
                }
                if (r1 < NODES) {
                    ps[ni][0] += fmaxf(fmaf(c[mi][ni][2], ii1, bx[ni]), 0.0f);
                    ps[ni][1] += fmaxf(fmaf(c[mi][ni][3], ii1, by[ni]), 0.0f);
                }
            }
        }
        #pragma unroll
        for (int off = 16; off >= 4; off >>= 1) {
            #pragma unroll
            for (int ni = 0; ni < 2; ni++) {
                ps[ni][0] += __shfl_down_sync(0xffffffffu, ps[ni][0], off);
                ps[ni][1] += __shfl_down_sync(0xffffffffu, ps[ni][1], off);
            }
        }
        if (lane < 4) {
            #pragma unroll
            for (int ni = 0; ni < 2; ni++) {
                int col = wn * 16 + ni * 8 + lane * 2;
                pool[wm * 128 + col]     = ps[ni][0];
                pool[wm * 128 + col + 1] = ps[ni][1];
            }
        }
    }
    __syncthreads();
    if (tid < HID) {
        float v = (pool[tid] + pool[128 + tid]) * (1.0f / 200.0f);
        bf16 h = __float2bfloat16(v);
        hgh[g * HID + tid] = h;
        hgl[g * HID + tid] = __float2bfloat16(v - __bfloat162float(h));
    }
}

// ===========================================================================
// Merged kernel: 512 CTAs x 512 threads. bid<16: pwl; else conv prologue;
// all: gnn for graph bid.
// ===========================================================================
__global__ void __launch_bounds__(512, 1) prep_gnn(
    const int* __restrict__ src, const int* __restrict__ dst,
    const float* __restrict__ W1, const float* __restrict__ b1,
    const float* __restrict__ W2, const float* __restrict__ b2,
    const float* __restrict__ Wa, const float* __restrict__ Wb,
    const float* __restrict__ Wc, const float* __restrict__ Wd,
    bf16* __restrict__ hgh, bf16* __restrict__ hgl)
{
    extern __shared__ unsigned char smraw[];
    const int bid = blockIdx.x;
    if (bid < 16) pwl_block(bid, smraw, W1, b1, W2);
    else          conv_block(bid - 16, 496, smraw, Wa, Wb, Wc, Wd);
    gnn_block(bid, smraw, src, dst, b2, hgh, hgl);
}

// ---------------------------------------------------------------------------
// Split-K bf16 hi/lo tensor-core GEMM: 32x64 tile, 256 threads, 2-stage
// pipeline. bias != nullptr -> fused bias+relu+bf16 hi/lo epilogue; else
// fp32 partials to part[z].
// ---------------------------------------------------------------------------
#define TSB 40

__global__ void __launch_bounds__(256) gemm_bf16(
    const bf16* __restrict__ Ah, const bf16* __restrict__ Al,
    const bf16* __restrict__ Bh, const bf16* __restrict__ Bl,
    float* __restrict__ part,
    const float* __restrict__ bias,
    bf16* __restrict__ Oh, bf16* __restrict__ Ol,
    int Ktot, int Kchunk, int Nc)
{
    __shared__ bf16 sAh[2][32 * TSB], sAl[2][32 * TSB];
    __shared__ bf16 sBh[2][64 * TSB], sBl[2][64 * TSB];

    const int tid  = threadIdx.x;
    const int lane = tid & 31;
    const int wid  = tid >> 5;
    const int wm   = wid & 1;
    const int wn   = wid >> 1;
    const int row0 = blockIdx.y * 32, col0 = blockIdx.x * 64;
    const int z    = blockIdx.z;
    const int kofs = z * Kchunk;

    const int th  = tid & 127;
    const int lr  = th >> 2;
    const int lc  = (th & 3) * 8;
    const bool pl = (tid < 128);

    const bf16* gA  = (pl ? Ah : Al) + (size_t)(row0 + lr) * Ktot + kofs + lc;
    const bf16* gB0 = (pl ? Bh : Bl) + (size_t)(col0 + lr) * Ktot + kofs + lc;
    const bf16* gB1 = (pl ? Bh : Bl) + (size_t)(col0 + 32 + lr) * Ktot + kofs + lc;
    bf16* dA0 = (pl ? sAh[0] : sAl[0]) + lr * TSB + lc;
    bf16* dB0 = (pl ? sBh[0] : sBl[0]) + lr * TSB + lc;
    bf16* dA1 = (pl ? sAh[1] : sAl[1]) + lr * TSB + lc;
    bf16* dB1 = (pl ? sBh[1] : sBl[1]) + lr * TSB + lc;

    float c[2][4];
    #pragma unroll
    for (int ni = 0; ni < 2; ni++)
        #pragma unroll
        for (int q = 0; q < 4; q++) c[ni][q] = 0.0f;

    cp16(dA0, gA);
    cp16(dB0, gB0);
    cp16(dB0 + 32 * TSB, gB1);
    cp_commit();

    const int nkt = Kchunk >> 5;
    const int frow = lane & 15;
    const int fk   = (lane >> 4) * 8;
    int buf = 0;

    for (int kt = 0; kt < nkt; kt++) {
        if (kt + 1 < nkt) {
            bf16* dA = buf ? dA0 : dA1;
            bf16* dB = buf ? dB0 : dB1;
            cp16(dA, gA + (size_t)(kt + 1) * 32);
            cp16(dB, gB0 + (size_t)(kt + 1) * 32);
            cp16(dB + 32 * TSB, gB1 + (size_t)(kt + 1) * 32);
            cp_commit();
            cp_wait<1>();
        } else {
            cp_wait<0>();
        }
        __syncthreads();

        #pragma unroll
        for (int ks = 0; ks < 32; ks += 16) {
            unsigned ah[4], al[4], bh[4], bl[4];
            {
                int ro = (wm * 16 + frow) * TSB + ks + fk;
                ldsm4(ah, &sAh[buf][ro]);
                ldsm4(al, &sAl[buf][ro]);
            }
            {
                int no = (wn * 16 + frow) * TSB + ks + fk;
                ldsm4(bh, &sBh[buf][no]);
                ldsm4(bl, &sBl[buf][no]);
            }
            mma_bf16(c[0], ah, bh[0], bh[2]);
            mma_bf16(c[1], ah, bh[1], bh[3]);
            mma_bf16(c[0], ah, bl[0], bl[2]);
            mma_bf16(c[1], ah, bl[1], bl[3]);
            mma_bf16(c[0], al, bh[0], bh[2]);
            mma_bf16(c[1], al, bh[1], bh[3]);
        }
        __syncthreads();
        buf ^= 1;
    }

    const int g  = lane >> 2;
    const int tg = lane & 3;
    if (bias) {
        #pragma unroll
        for (int ni = 0; ni < 2; ni++) {
            int r  = row0 + wm * 16 + g;
            int cc = col0 + wn * 16 + ni * 8 + tg * 2;
            float2 bv = *(const float2*)(bias + cc);
            #pragma unroll
            for (int half = 0; half < 2; half++) {
                int rr = r + half * 8;
                float vx = fmaxf(c[ni][half * 2 + 0] + bv.x, 0.0f);
                float vy = fmaxf(c[ni][half * 2 + 1] + bv.y, 0.0f);
                bf16 hx = __float2bfloat16(vx);
                bf16 hy = __float2bfloat16(vy);
                *(__nv_bfloat162*)(Oh + (size_t)rr * Nc + cc) =
                    __halves2bfloat162(hx, hy);
                *(__nv_bfloat162*)(Ol + (size_t)rr * Nc + cc) =
                    __halves2bfloat162(
                        __float2bfloat16(vx - __bfloat162float(hx)),
                        __float2bfloat16(vy - __bfloat162float(hy)));
            }
        }
    } else {
        float* po = part + (size_t)z * 512 * Nc;
        #pragma unroll
        for (int ni = 0; ni < 2; ni++) {
            int r  = row0 + wm * 16 + g;
            int cc = col0 + wn * 16 + ni * 8 + tg * 2;
            *(float2*)(po + (size_t)r * Nc + cc)       = make_float2(c[ni][0], c[ni][1]);
            *(float2*)(po + (size_t)(r + 8) * Nc + cc) = make_float2(c[ni][2], c[ni][3]);
        }
    }
}

// ---------------------------------------------------------------------------
// Combine split-K partials: out = relu(sum_s part[s] + bias) -> bf16 hi/lo.
// ---------------------------------------------------------------------------
__global__ void __launch_bounds__(256) combine_relu(
    const float* __restrict__ part, int S, int zstride,
    const float* __restrict__ bias,
    bf16* __restrict__ Oh, bf16* __restrict__ Ol,
    int Nc, int total)
{
    int i2 = (blockIdx.x * 256 + threadIdx.x) * 2;
    if (i2 >= total) return;
    float2 s = *(const float2*)(part + i2);
    for (int z = 1; z < S; z++) {
        float2 p = *(const float2*)(part + (size_t)z * zstride + i2);
        s.x += p.x; s.y += p.y;
    }
    int col = i2 % Nc;
    float2 bv = *(const float2*)(bias + col);
    float vx = fmaxf(s.x + bv.x, 0.0f);
    float vy = fmaxf(s.y + bv.y, 0.0f);
    bf16 hx = __float2bfloat16(vx);
    bf16 hy = __float2bfloat16(vy);
    *(__nv_bfloat162*)(Oh + i2) = __halves2bfloat162(hx, hy);
    *(__nv_bfloat162*)(Ol + i2) = __halves2bfloat162(
        __float2bfloat16(vx - __bfloat162float(hx)),
        __float2bfloat16(vy - __bfloat162float(hy)));
}

// ---------------------------------------------------------------------------
// Final layer: reads layer-d fp32 partials directly (sum + bd + relu inline),
// computes softmax head. Also resets cross-kernel flag for next replay.
// ---------------------------------------------------------------------------
__global__ void __launch_bounds__(256) head_softmax(
    const float* __restrict__ part,   // 4 x [512 x 512] fp32 partials
    const float* __restrict__ bd,
    const float* __restrict__ We, const float* __restrict__ be,
    float* __restrict__ out)
{
    if (blockIdx.x == 0 && threadIdx.x == 0) g_pwl_flag = 0;

    __shared__ float Ws[512 * 10];
    const int tid = threadIdx.x;
    for (int i = tid; i < 512 * 10; i += 256) Ws[i] = We[i];
    __syncthreads();
    const int lane = tid & 31, w = tid >> 5;
    const int row = blockIdx.x * 8 + w;
    const size_t D = 512 * 512;
    const float* p0 = part + (size_t)row * 512;

    float acc[10];
    #pragma unroll
    for (int c = 0; c < 10; c++) acc[c] = 0.0f;
    for (int k = lane; k < 512; k += 32) {
        float s = p0[k] + p0[k + D] + p0[k + 2 * D] + p0[k + 3 * D];
        float a = fmaxf(s + bd[k], 0.0f);
        #pragma unroll
        for (int c = 0; c < 10; c++) acc[c] = fmaf(a, Ws[k * 10 + c], acc[c]);
    }
    #pragma unroll
    for (int c = 0; c < 10; c++) {
        #pragma unroll
        for (int o = 16; o > 0; o >>= 1)
            acc[c] += __shfl_xor_sync(0xffffffffu, acc[c], o);
    }
    if (lane == 0) {
        float v[10], mx = -1e30f;
        #pragma unroll
        for (int c = 0; c < 10; c++) { v[c] = acc[c] + be[c]; mx = fmaxf(mx, v[c]); }
        float s = 0.0f;
        #pragma unroll
        for (int c = 0; c < 10; c++) { v[c] = __expf(v[c] - mx); s += v[c]; }
        float inv = 1.0f / s;
        #pragma unroll
        for (int c = 0; c < 10; c++) out[row * 10 + c] = v[c] * inv;
    }
}

// ---------------------------------------------------------------------------
extern "C" void kernel_launch(void* const* d_in, const int* in_sizes, int n_in,
                              void* d_out, int out_size)
{
    const int*   src = (const int*)  d_in[0];
    const int*   dst = (const int*)  d_in[1];
    const float* W1  = (const float*)d_in[2];
    const float* b1  = (const float*)d_in[3];
    const float* W2  = (const float*)d_in[4];
    const float* b2  = (const float*)d_in[5];
    const float* Wa  = (const float*)d_in[6];
    const float* ba  = (const float*)d_in[7];
    const float* Wb  = (const float*)d_in[8];
    const float* bb  = (const float*)d_in[9];
    const float* Wc  = (const float*)d_in[10];
    const float* bc  = (const float*)d_in[11];
    const float* Wd  = (const float*)d_in[12];
    const float* bd  = (const float*)d_in[13];
    const float* We  = (const float*)d_in[14];
    const float* be  = (const float*)d_in[15];
    float* out = (float*)d_out;

    bf16 *hgh, *hgl, *x1h, *x1l, *x2h, *x2l, *x3h, *x3l;
    bf16 *wah, *wal, *wbh, *wbl, *wch, *wcl, *wdh, *wdl;
    float* part;
    cudaGetSymbolAddress((void**)&hgh, g_hgh); cudaGetSymbolAddress((void**)&hgl, g_hgl);
    cudaGetSymbolAddress((void**)&x1h, g_x1h); cudaGetSymbolAddress((void**)&x1l, g_x1l);
    cudaGetSymbolAddress((void**)&x2h, g_x2h); cudaGetSymbolAddress((void**)&x2l, g_x2l);
    cudaGetSymbolAddress((void**)&x3h, g_x3h); cudaGetSymbolAddress((void**)&x3l, g_x3l);
    cudaGetSymbolAddress((void**)&wah, g_wta_h); cudaGetSymbolAddress((void**)&wal, g_wta_l);
    cudaGetSymbolAddress((void**)&wbh, g_wtb_h); cudaGetSymbolAddress((void**)&wbl, g_wtb_l);
    cudaGetSymbolAddress((void**)&wch, g_wtc_h); cudaGetSymbolAddress((void**)&wcl, g_wtc_l);
    cudaGetSymbolAddress((void**)&wdh, g_wtd_h); cudaGetSymbolAddress((void**)&wdl, g_wtd_l);
    cudaGetSymbolAddress((void**)&part, g_part);

    const int SMEM = 224 * CS * 2 + 2 * 208 * TSN * 2
                   + 4 * 224 * 4 + 256 * 4 + 448 * 4 + 224;
    cudaFuncSetAttribute(prep_gnn, cudaFuncAttributeMaxDynamicSharedMemorySize, SMEM);

    prep_gnn<<<512, 512, SMEM>>>(src, dst, W1, b1, W2, b2, Wa, Wb, Wc, Wd, hgh, hgl);

    // layer a: K=128, single chunk, fused epilogue
    gemm_bf16<<<dim3(8, 16, 1), 256>>>(hgh, hgl, wah, wal, nullptr, ba,
                                       x1h, x1l, 128, 128, 512);
    // layer b: K=512, split 2 -> grid 512
    gemm_bf16<<<dim3(16, 16, 2), 256>>>(x1h, x1l, wbh, wbl, part, nullptr,
                                        nullptr, nullptr, 512, 256, 1024);
    combine_relu<<<1024, 256>>>(part, 2, 512 * 1024, bb, x2h, x2l, 1024, 512 * 1024);
    // layer c: K=1024, split 4 -> grid 1024
    gemm_bf16<<<dim3(16, 16, 4), 256>>>(x2h, x2l, wch, wcl, part, nullptr,
                                        nullptr, nullptr, 1024, 256, 1024);
    combine_relu<<<1024, 256>>>(part, 4, 512 * 1024, bc, x3h, x3l, 1024, 512 * 1024);
    // layer d: K=1024, split 4 -> grid 512, partials consumed by head
    gemm_bf16<<<dim3(8, 16, 4), 256>>>(x3h, x3l, wdh, wdl, part, nullptr,
                                       nullptr, nullptr, 1024, 256, 512);

    head_softmax<<<64, 256>>>(part, bd, We, be, out);
}

// round 15
// speedup vs baseline: 1.1125x; 1.0721x over previous
#include <cuda_runtime.h>
#include <cuda_bf16.h>
#include <cuda_fp16.h>

#define NG      512
#define NODES   200
#define EDGES   6400
#define HID     128

typedef __nv_bfloat16 bf16;

// ---- activation buffers (bf16 hi/lo pairs) --------------------------------
__device__ bf16 g_hgh[NG * HID],  g_hgl[NG * HID];
__device__ bf16 g_x1h[NG * 512],  g_x1l[NG * 512];
__device__ bf16 g_x2h[NG * 1024], g_x2l[NG * 1024];
__device__ bf16 g_x3h[NG * 1024], g_x3l[NG * 1024];

// ---- pre-converted transposed weights [N][K] bf16 hi/lo -------------------
__device__ bf16 g_wta_h[512 * 128],   g_wta_l[512 * 128];
__device__ bf16 g_wtb_h[1024 * 512],  g_wtb_l[1024 * 512];
__device__ bf16 g_wtc_h[1024 * 1024], g_wtc_l[1024 * 1024];
__device__ bf16 g_wtd_h[512 * 1024],  g_wtd_l[512 * 1024];

// ---- split-K partial scratch (fp32) ----------------------------------------
__device__ float g_part[4 * 512 * 1024];

// ---- PWL tables + readiness flag (reset by head_softmax each launch) ------
__device__ float g_csorted[128];
__device__ float g_alpha[129 * 128];
__device__ float g_beta[129 * 128];
__device__ unsigned g_pwl_flag = 0;

// ---- asm helpers -----------------------------------------------------------
__device__ __forceinline__ void cp16(void* smem, const void* gmem) {
    unsigned sa = (unsigned)__cvta_generic_to_shared(smem);
    asm volatile("cp.async.cg.shared.global [%0], [%1], 16;\n" :: "r"(sa), "l"(gmem));
}
__device__ __forceinline__ void cp_commit() {
    asm volatile("cp.async.commit_group;\n");
}
template <int N>
__device__ __forceinline__ void cp_wait() {
    asm volatile("cp.async.wait_group %0;\n" :: "n"(N));
}
__device__ __forceinline__ void ldsm4(unsigned r[4], const void* p) {
    unsigned a = (unsigned)__cvta_generic_to_shared(p);
    asm volatile("ldmatrix.sync.aligned.m8n8.x4.shared.b16 {%0,%1,%2,%3}, [%4];\n"
                 : "=r"(r[0]), "=r"(r[1]), "=r"(r[2]), "=r"(r[3]) : "r"(a));
}
__device__ __forceinline__ void ldsm4t(unsigned r[4], const void* p) {
    unsigned a = (unsigned)__cvta_generic_to_shared(p);
    asm volatile("ldmatrix.sync.aligned.m8n8.x4.trans.shared.b16 {%0,%1,%2,%3}, [%4];\n"
                 : "=r"(r[0]), "=r"(r[1]), "=r"(r[2]), "=r"(r[3]) : "r"(a));
}
__device__ __forceinline__ void mma_bf16(float c[4], const unsigned a[4],
                                         unsigned b0, unsigned b1) {
    asm volatile(
        "mma.sync.aligned.m16n8k16.row.col.f32.bf16.bf16.f32 "
        "{%0,%1,%2,%3}, {%4,%5,%6,%7}, {%8,%9}, {%0,%1,%2,%3};\n"
        : "+f"(c[0]), "+f"(c[1]), "+f"(c[2]), "+f"(c[3])
        : "r"(a[0]), "r"(a[1]), "r"(a[2]), "r"(a[3]), "r"(b0), "r"(b1));
}
__device__ __forceinline__ void mma_f16(float c[4], const unsigned a[4],
                                        unsigned b0, unsigned b1) {
    asm volatile(
        "mma.sync.aligned.m16n8k16.row.col.f32.f16.f16.f32 "
        "{%0,%1,%2,%3}, {%4,%5,%6,%7}, {%8,%9}, {%0,%1,%2,%3};\n"
        : "+f"(c[0]), "+f"(c[1]), "+f"(c[2]), "+f"(c[3])
        : "r"(a[0]), "r"(a[1]), "r"(a[2]), "r"(a[3]), "r"(b0), "r"(b1));
}

// ===========================================================================
// PWL table builder (bids 0..15, 8 segments each). tid<128 active.
// ===========================================================================
__device__ void pwl_block(int p, unsigned char* smraw,
    const float* __restrict__ W1, const float* __restrict__ b1,
    const float* __restrict__ W2)
{
    float* sW2 = (float*)smraw;            // 16384 floats
    float* sc  = sW2 + 16384;
    float* sw  = sc + 128;
    float* sb  = sw + 128;
    float* ssc = sb + 128;
    int*  sidx = (int*)(ssc + 128);
    const int tid = threadIdx.x;

    for (int i = tid; i < 4096; i += 512)
        ((float4*)sW2)[i] = ((const float4*)W2)[i];
    if (tid < 128) {
        float w = W1[tid], b = b1[tid];
        sw[tid] = w; sb[tid] = b;
        sc[tid] = (w != 0.0f) ? (-b / w) : __int_as_float(0x7f800000);
    }
    __syncthreads();
    if (tid < 128) {
        float c = sc[tid];
        int r = 0;
        for (int j = 0; j < 128; j++) {
            float cj = sc[j];
            if (cj < c || (cj == c && j < tid)) r++;
        }
        sidx[r] = tid;
        ssc[r]  = c;
    }
    __syncthreads();
    if (tid < 128) {
        if (p == 0) g_csorted[tid] = ssc[tid];
        const int j  = tid;
        const int s0 = p * 8;
        float alpha = 0.0f, beta = 0.0f;
        for (int r = 0; r < 128; r++) {
            int k = sidx[r];
            float w = sw[k], b = sb[k];
            float W2kj = sW2[k * 128 + j];
            if (w == 0.0f) { if (b > 0.0f) beta += b * W2kj; continue; }
            bool active = (w > 0.0f) ? (r < s0) : (r >= s0);
            if (active) { alpha = fmaf(w, W2kj, alpha); beta = fmaf(b, W2kj, beta); }
        }
        for (int s = s0; s < s0 + 8; s++) {
            g_alpha[s * 128 + j] = alpha;
            g_beta[s * 128 + j]  = beta;
            int k = sidx[s];
            float w = sw[k], b = sb[k];
            float W2kj = sW2[k * 128 + j];
            float f = (w > 0.0f) ? 1.0f : ((w < 0.0f) ? -1.0f : 0.0f);
            alpha = fmaf(f * w, W2kj, alpha);
            beta  = fmaf(f * b, W2kj, beta);
        }
        if (p == 15) {
            g_alpha[128 * 128 + j] = alpha;
            g_beta[128 * 128 + j]  = beta;
        }
    }
    __syncthreads();
    if (tid == 0) {
        __threadfence();
        atomicAdd(&g_pwl_flag, 1u);
    }
}

// ===========================================================================
// Weight-convert prologue: grid-stride over 2112 32x32 transpose tiles.
// ===========================================================================
__device__ void conv_block(int w, int stride, unsigned char* smraw,
    const float* __restrict__ Wa, const float* __restrict__ Wb,
    const float* __restrict__ Wc, const float* __restrict__ Wd)
{
    float (*tile)[33] = (float(*)[33])smraw;
    const int tid = threadIdx.x;
    const int c = tid & 31, r = tid >> 5;

    for (int t = w; t < 2112; t += stride) {
        const float* W; bf16 *Oh, *Ol; int K, N, tl, tn;
        if (t < 64)        { W = Wa; Oh = g_wta_h; Ol = g_wta_l; K = 128;  N = 512;  tl = t;        tn = 16; }
        else if (t < 576)  { W = Wb; Oh = g_wtb_h; Ol = g_wtb_l; K = 512;  N = 1024; tl = t - 64;   tn = 32; }
        else if (t < 1600) { W = Wc; Oh = g_wtc_h; Ol = g_wtc_l; K = 1024; N = 1024; tl = t - 576;  tn = 32; }
        else               { W = Wd; Oh = g_wtd_h; Ol = g_wtd_l; K = 1024; N = 512;  tl = t - 1600; tn = 16; }
        int nb = (tl % tn) * 32, kb = (tl / tn) * 32;
        #pragma unroll
        for (int j = 0; j < 2; j++)
            tile[r + j * 16][c] = W[(size_t)(kb + r + j * 16) * N + nb + c];
        __syncthreads();
        #pragma unroll
        for (int j = 0; j < 2; j++) {
            int n = nb + r + j * 16;
            float v = tile[c][r + j * 16];
            bf16 h = __float2bfloat16(v);
            Oh[(size_t)n * K + kb + c] = h;
            Ol[(size_t)n * K + kb + c] = __float2bfloat16(v - __bfloat162float(h));
        }
        __syncthreads();
    }
}

// ===========================================================================
// Per-graph GNN block v3: u4 counts only + on-the-fly fp16 expansion SpMM.
// SMEM = 106,304 B -> 2 CTAs/SM.
// ===========================================================================
#define U4ROWW 27
#define TSN 136   // th row stride (halfs)
#define AST 24    // A-staging row stride (halfs)

__device__ void gnn_block(int g, unsigned char* smraw,
    const int* __restrict__ src, const int* __restrict__ dst,
    const float* __restrict__ b2,
    bf16* __restrict__ hgh, bf16* __restrict__ hgl)
{
    unsigned* Cu  = (unsigned*)smraw;                    // [200][27] u32
    __half*   th  = (__half*)(Cu + 200 * U4ROWW);        // [208][136]
    __half*   Ast = th + 208 * TSN;                      // [2][224][24]
    float* s_a  = (float*)(Ast + 2 * 224 * AST);         // 224
    float* s_ii = s_a + 224;
    float* s_io = s_ii + 224;
    float* s_s  = s_io + 224;
    float* pool = s_s + 224;                             // 256
    float* colp = pool + 256;                            // 448
    unsigned char* seg = (unsigned char*)(colp + 448);   // 224

    const int tid   = threadIdx.x;
    const int ebase = g * EDGES;
    const int nbase = g * NODES;

    __syncthreads();   // smem handoff from pwl/conv prologue

    // --- 1. zero u4 counts + th pad rows (200..207) ---
    {
        uint4 z = {0, 0, 0, 0};
        uint4* u4a = (uint4*)Cu;                     // 1350 uint4 (5400 u32)
        for (int i = tid; i < 1350; i += 512) u4a[i] = z;
        uint4* tp = (uint4*)(th + 200 * TSN);        // 8*136 halfs = 136 uint4
        for (int i = tid; i < 136; i += 512) tp[i] = z;
    }
    __syncthreads();

    // --- 2. count matrix: one native u32 atomic per edge (4-bit cells) ---
    for (int e = tid; e < EDGES; e += 512) {
        int sl = src[ebase + e] - nbase;
        int dl = dst[ebase + e] - nbase;
        atomicAdd(&Cu[dl * U4ROWW + (sl >> 3)], 1u << (4 * (sl & 7)));
    }
    __syncthreads();

    // --- 3. row sums via nibble SWAR ---
    if (tid < 224) {
        float sum = 0.0f;
        if (tid < 200) {
            unsigned s = 0;
            const unsigned* row = Cu + tid * U4ROWW;
            #pragma unroll
            for (int w = 0; w < U4ROWW; w++) {
                unsigned word = row[w];
                unsigned b = (word & 0x0F0F0F0Fu) + ((word >> 4) & 0x0F0F0F0Fu);
                s += (b & 0xFFu) + ((b >> 8) & 0xFFu) + ((b >> 16) & 0xFFu) + (b >> 24);
            }
            sum = (float)s;
        }
        s_a[tid]  = sum;
        s_ii[tid] = rsqrtf(fmaxf(sum, 1.0f));
    }
    __syncthreads();

    // --- 4. col sums (2-way split over rows) ---
    if (tid < 432) {
        int cc = tid % 216, hf = tid / 216;
        int w = cc >> 3, sh = 4 * (cc & 7);
        unsigned s = 0;
        for (int d = hf * 100; d < hf * 100 + 100; d++)
            s += (Cu[d * U4ROWW + w] >> sh) & 15u;
        colp[tid] = (float)s;
    }
    __syncthreads();
    if (tid < 216) {
        float sum = colp[tid] + colp[216 + tid];
        float io = rsqrtf(fmaxf(sum, 1.0f));
        s_io[tid] = io;
        s_s[tid]  = s_a[tid] * io;
    }
    __syncthreads();

    // --- wait for PWL tables ---
    if (tid == 0) {
        unsigned v;
        do {
            asm volatile("ld.global.acquire.gpu.u32 %0, [%1];"
                         : "=r"(v) : "l"(&g_pwl_flag));
            if (v < 16u) __nanosleep(64);
        } while (v < 16u);
    }
    __syncthreads();

    // --- 5. layer-1 matvec from u4 (2-way split) + segment search ---
    if (tid < 400) {
        int d = tid % 200, hf = tid / 200;
        int w0 = hf ? 13 : 0, w1 = hf ? 27 : 13;
        float sum = 0.0f;
        for (int w = w0; w < w1; w++) {
            unsigned word = Cu[d * U4ROWW + w];
            const float* ss = s_s + w * 8;
            #pragma unroll
            for (int j = 0; j < 8; j++)
                sum += (float)((word >> (4 * j)) & 15u) * ss[j];
        }
        colp[tid] = sum;
    }
    __syncthreads();
    if (tid < NODES) {
        float a = (colp[tid] + colp[200 + tid]) * s_ii[tid];
        s_a[tid] = a;
        int lo = 0, hi = 128;
        while (lo < hi) {
            int m = (lo + hi) >> 1;
            if (g_csorted[m] < a) lo = m + 1; else hi = m;
        }
        seg[tid] = (unsigned char)lo;
    }
    __syncthreads();

    // --- 6. t (fp16, single precision level) ---
    for (int idx = tid; idx < NODES * 32; idx += 512) {
        int i = idx >> 5, q = idx & 31;
        float a  = s_a[i];
        float io = s_io[i];
        int   s  = seg[i];
        float4 al = ((const float4*)(g_alpha + s * 128))[q];
        float4 be = ((const float4*)(g_beta  + s * 128))[q];
        float v0 = fmaf(al.x, a, be.x) * io;
        float v1 = fmaf(al.y, a, be.y) * io;
        float v2 = fmaf(al.z, a, be.z) * io;
        float v3 = fmaf(al.w, a, be.w) * io;
        __half2* dh = (__half2*)(th + i * TSN + q * 4);
        dh[0] = __floats2half2_rn(v0, v1);
        dh[1] = __floats2half2_rn(v2, v3);
    }
    __syncthreads();

    // --- 7. MMA: two 64-col passes, u4->fp16 A expansion per k-tile ---
    const int lane = tid & 31;
    const int wid  = tid >> 5;
    const int wm   = wid & 1;          // 2 m-groups x 112 rows
    const int wn   = wid >> 1;         // 8 n-groups x 8 cols per pass
    const int npg  = wn >> 1;          // 16-col ldsm group
    const int sel  = wn & 1;           // n8 half within group

    const int aRow = wm * 112 + (lane & 15);
    const int aCol = ((lane >> 4) & 1) * 8;
    const int bRow = (lane & 7) + ((lane >> 4) & 1) * 8;
    const int gg   = lane >> 2;
    const int tg   = lane & 3;

    #pragma unroll 1
    for (int np = 0; np < 2; np++) {
        float c[7][4];
        #pragma unroll
        for (int mi = 0; mi < 7; mi++)
            #pragma unroll
            for (int q = 0; q < 4; q++) c[mi][q] = 0.0f;

        const int bColB = np * 64 + npg * 16 + ((lane >> 3) & 1) * 8;
        int buf = 0;
        #pragma unroll 1
        for (int kt = 0; kt < 13; kt++) {
            // expand u4 rows into Ast[buf]: 224 rows x 16 k
            __half* astb = Ast + buf * 224 * AST;
            for (int t = tid; t < 448; t += 512) {
                int r = t >> 1, wi = t & 1;
                unsigned word = (r < 200) ? Cu[r * U4ROWW + kt * 2 + wi] : 0u;
                __half2* o = (__half2*)(astb + r * AST + wi * 8);
                o[0] = __floats2half2_rn((float)(word & 15u),
                                         (float)((word >> 4) & 15u));
                o[1] = __floats2half2_rn((float)((word >> 8) & 15u),
                                         (float)((word >> 12) & 15u));
                o[2] = __floats2half2_rn((float)((word >> 16) & 15u),
                                         (float)((word >> 20) & 15u));
                o[3] = __floats2half2_rn((float)((word >> 24) & 15u),
                                         (float)((word >> 28) & 15u));
            }
            __syncthreads();

            unsigned bh[4];
            ldsm4t(bh, th + (kt * 16 + bRow) * TSN + bColB);
            unsigned b0 = sel ? bh[1] : bh[0];
            unsigned b1 = sel ? bh[3] : bh[2];
            #pragma unroll
            for (int mi = 0; mi < 7; mi++) {
                unsigned af[4];
                ldsm4(af, astb + (aRow + mi * 16) * AST + aCol);
                mma_f16(c[mi], af, b0, b1);
            }
            buf ^= 1;
        }

        // epilogue for this pass: relu + pool partials
        {
            int colb = np * 64 + npg * 16 + sel * 8 + tg * 2;
            float2 bv = *(const float2*)(b2 + colb);
            float ps0 = 0.0f, ps1 = 0.0f;
            #pragma unroll
            for (int mi = 0; mi < 7; mi++) {
                int r0 = wm * 112 + mi * 16 + gg;
                int r1 = r0 + 8;
                if (r0 < NODES) {
                    float ii0 = s_ii[r0];
                    ps0 += fmaxf(fmaf(c[mi][0], ii0, bv.x), 0.0f);
                    ps1 += fmaxf(fmaf(c[mi][1], ii0, bv.y), 0.0f);
                }
                if (r1 < NODES) {
                    float ii1 = s_ii[r1];
                    ps0 += fmaxf(fmaf(c[mi][2], ii1, bv.x), 0.0f);
                    ps1 += fmaxf(fmaf(c[mi][3], ii1, bv.y), 0.0f);
                }
            }
            #pragma unroll
            for (int off = 16; off >= 4; off >>= 1) {
                ps0 += __shfl_down_sync(0xffffffffu, ps0, off);
                ps1 += __shfl_down_sync(0xffffffffu, ps1, off);
            }
            if (lane < 4) {
                int col = np * 64 + npg * 16 + sel * 8 + lane * 2;
                pool[wm * 128 + col]     = ps0;
                pool[wm * 128 + col + 1] = ps1;
            }
        }
        __syncthreads();   // pool writes done; Ast reusable next pass
    }

    if (tid < HID) {
        float v = (pool[tid] + pool[128 + tid]) * (1.0f / 200.0f);
        bf16 h = __float2bfloat16(v);
        hgh[g * HID + tid] = h;
        hgl[g * HID + tid] = __float2bfloat16(v - __bfloat162float(h));
    }
}

// ===========================================================================
// Merged kernel: 512 CTAs x 512 threads, 2 CTAs/SM.
// bid<16: pwl; else conv prologue; all: gnn for graph bid.
// ===========================================================================
__global__ void __launch_bounds__(512, 2) prep_gnn(
    const int* __restrict__ src, const int* __restrict__ dst,
    const float* __restrict__ W1, const float* __restrict__ b1,
    const float* __restrict__ W2, const float* __restrict__ b2,
    const float* __restrict__ Wa, const float* __restrict__ Wb,
    const float* __restrict__ Wc, const float* __restrict__ Wd,
    bf16* __restrict__ hgh, bf16* __restrict__ hgl)
{
    extern __shared__ unsigned char smraw[];
    const int bid = blockIdx.x;
    if (bid < 16) pwl_block(bid, smraw, W1, b1, W2);
    else          conv_block(bid - 16, 496, smraw, Wa, Wb, Wc, Wd);
    gnn_block(bid, smraw, src, dst, b2, hgh, hgl);
}

// ---------------------------------------------------------------------------
// Split-K bf16 hi/lo tensor-core GEMM (unchanged from R14 winner).
// ---------------------------------------------------------------------------
#define TSB 40

__global__ void __launch_bounds__(256) gemm_bf16(
    const bf16* __restrict__ Ah, const bf16* __restrict__ Al,
    const bf16* __restrict__ Bh, const bf16* __restrict__ Bl,
    float* __restrict__ part,
    const float* __restrict__ bias,
    bf16* __restrict__ Oh, bf16* __restrict__ Ol,
    int Ktot, int Kchunk, int Nc)
{
    __shared__ bf16 sAh[2][32 * TSB], sAl[2][32 * TSB];
    __shared__ bf16 sBh[2][64 * TSB], sBl[2][64 * TSB];

    const int tid  = threadIdx.x;
    const int lane = tid & 31;
    const int wid  = tid >> 5;
    const int wm   = wid & 1;
    const int wn   = wid >> 1;
    const int row0 = blockIdx.y * 32, col0 = blockIdx.x * 64;
    const int z    = blockIdx.z;
    const int kofs = z * Kchunk;

    const int th  = tid & 127;
    const int lr  = th >> 2;
    const int lc  = (th & 3) * 8;
    const bool pl = (tid < 128);

    const bf16* gA  = (pl ? Ah : Al) + (size_t)(row0 + lr) * Ktot + kofs + lc;
    const bf16* gB0 = (pl ? Bh : Bl) + (size_t)(col0 + lr) * Ktot + kofs + lc;
    const bf16* gB1 = (pl ? Bh : Bl) + (size_t)(col0 + 32 + lr) * Ktot + kofs + lc;
    bf16* dA0 = (pl ? sAh[0] : sAl[0]) + lr * TSB + lc;
    bf16* dB0 = (pl ? sBh[0] : sBl[0]) + lr * TSB + lc;
    bf16* dA1 = (pl ? sAh[1] : sAl[1]) + lr * TSB + lc;
    bf16* dB1 = (pl ? sBh[1] : sBl[1]) + lr * TSB + lc;

    float c[2][4];
    #pragma unroll
    for (int ni = 0; ni < 2; ni++)
        #pragma unroll
        for (int q = 0; q < 4; q++) c[ni][q] = 0.0f;

    cp16(dA0, gA);
    cp16(dB0, gB0);
    cp16(dB0 + 32 * TSB, gB1);
    cp_commit();

    const int nkt = Kchunk >> 5;
    const int frow = lane & 15;
    const int fk   = (lane >> 4) * 8;
    int buf = 0;

    for (int kt = 0; kt < nkt; kt++) {
        if (kt + 1 < nkt) {
            bf16* dA = buf ? dA0 : dA1;
            bf16* dB = buf ? dB0 : dB1;
            cp16(dA, gA + (size_t)(kt + 1) * 32);
            cp16(dB, gB0 + (size_t)(kt + 1) * 32);
            cp16(dB + 32 * TSB, gB1 + (size_t)(kt + 1) * 32);
            cp_commit();
            cp_wait<1>();
        } else {
            cp_wait<0>();
        }
        __syncthreads();

        #pragma unroll
        for (int ks = 0; ks < 32; ks += 16) {
            unsigned ah[4], al[4], bh[4], bl[4];
            {
                int ro = (wm * 16 + frow) * TSB + ks + fk;
                ldsm4(ah, &sAh[buf][ro]);
                ldsm4(al, &sAl[buf][ro]);
            }
            {
                int no = (wn * 16 + frow) * TSB + ks + fk;
                ldsm4(bh, &sBh[buf][no]);
                ldsm4(bl, &sBl[buf][no]);
            }
            mma_bf16(c[0], ah, bh[0], bh[2]);
            mma_bf16(c[1], ah, bh[1], bh[3]);
            mma_bf16(c[0], ah, bl[0], bl[2]);
            mma_bf16(c[1], ah, bl[1], bl[3]);
            mma_bf16(c[0], al, bh[0], bh[2]);
            mma_bf16(c[1], al, bh[1], bh[3]);
        }
        __syncthreads();
        buf ^= 1;
    }

    const int g  = lane >> 2;
    const int tg = lane & 3;
    if (bias) {
        #pragma unroll
        for (int ni = 0; ni < 2; ni++) {
            int r  = row0 + wm * 16 + g;
            int cc = col0 + wn * 16 + ni * 8 + tg * 2;
            float2 bv = *(const float2*)(bias + cc);
            #pragma unroll
            for (int half = 0; half < 2; half++) {
                int rr = r + half * 8;
                float vx = fmaxf(c[ni][half * 2 + 0] + bv.x, 0.0f);
                float vy = fmaxf(c[ni][half * 2 + 1] + bv.y, 0.0f);
                bf16 hx = __float2bfloat16(vx);
                bf16 hy = __float2bfloat16(vy);
                *(__nv_bfloat162*)(Oh + (size_t)rr * Nc + cc) =
                    __halves2bfloat162(hx, hy);
                *(__nv_bfloat162*)(Ol + (size_t)rr * Nc + cc) =
                    __halves2bfloat162(
                        __float2bfloat16(vx - __bfloat162float(hx)),
                        __float2bfloat16(vy - __bfloat162float(hy)));
            }
        }
    } else {
        float* po = part + (size_t)z * 512 * Nc;
        #pragma unroll
        for (int ni = 0; ni < 2; ni++) {
            int r  = row0 + wm * 16 + g;
            int cc = col0 + wn * 16 + ni * 8 + tg * 2;
            *(float2*)(po + (size_t)r * Nc + cc)       = make_float2(c[ni][0], c[ni][1]);
            *(float2*)(po + (size_t)(r + 8) * Nc + cc) = make_float2(c[ni][2], c[ni][3]);
        }
    }
}

// ---------------------------------------------------------------------------
// Combine split-K partials: out = relu(sum_s part[s] + bias) -> bf16 hi/lo.
// ---------------------------------------------------------------------------
__global__ void __launch_bounds__(256) combine_relu(
    const float* __restrict__ part, int S, int zstride,
    const float* __restrict__ bias,
    bf16* __restrict__ Oh, bf16* __restrict__ Ol,
    int Nc, int total)
{
    int i2 = (blockIdx.x * 256 + threadIdx.x) * 2;
    if (i2 >= total) return;
    float2 s = *(const float2*)(part + i2);
    for (int z = 1; z < S; z++) {
        float2 p = *(const float2*)(part + (size_t)z * zstride + i2);
        s.x += p.x; s.y += p.y;
    }
    int col = i2 % Nc;
    float2 bv = *(const float2*)(bias + col);
    float vx = fmaxf(s.x + bv.x, 0.0f);
    float vy = fmaxf(s.y + bv.y, 0.0f);
    bf16 hx = __float2bfloat16(vx);
    bf16 hy = __float2bfloat16(vy);
    *(__nv_bfloat162*)(Oh + i2) = __halves2bfloat162(hx, hy);
    *(__nv_bfloat162*)(Ol + i2) = __halves2bfloat162(
        __float2bfloat16(vx - __bfloat162float(hx)),
        __float2bfloat16(vy - __bfloat162float(hy)));
}

// ---------------------------------------------------------------------------
// Final layer: reads layer-d fp32 partials directly; softmax head.
// ---------------------------------------------------------------------------
__global__ void __launch_bounds__(256) head_softmax(
    const float* __restrict__ part,
    const float* __restrict__ bd,
    const float* __restrict__ We, const float* __restrict__ be,
    float* __restrict__ out)
{
    if (blockIdx.x == 0 && threadIdx.x == 0) g_pwl_flag = 0;

    __shared__ float Ws[512 * 10];
    const int tid = threadIdx.x;
    for (int i = tid; i < 512 * 10; i += 256) Ws[i] = We[i];
    __syncthreads();
    const int lane = tid & 31, w = tid >> 5;
    const int row = blockIdx.x * 8 + w;
    const size_t D = 512 * 512;
    const float* p0 = part + (size_t)row * 512;

    float acc[10];
    #pragma unroll
    for (int c = 0; c < 10; c++) acc[c] = 0.0f;
    for (int k = lane; k < 512; k += 32) {
        float s = p0[k] + p0[k + D] + p0[k + 2 * D] + p0[k + 3 * D];
        float a = fmaxf(s + bd[k], 0.0f);
        #pragma unroll
        for (int c = 0; c < 10; c++) acc[c] = fmaf(a, Ws[k * 10 + c], acc[c]);
    }
    #pragma unroll
    for (int c = 0; c < 10; c++) {
        #pragma unroll
        for (int o = 16; o > 0; o >>= 1)
            acc[c] += __shfl_xor_sync(0xffffffffu, acc[c], o);
    }
    if (lane == 0) {
        float v[10], mx = -1e30f;
        #pragma unroll
        for (int c = 0; c < 10; c++) { v[c] = acc[c] + be[c]; mx = fmaxf(mx, v[c]); }
        float s = 0.0f;
        #pragma unroll
        for (int c = 0; c < 10; c++) { v[c] = __expf(v[c] - mx); s += v[c]; }
        float inv = 1.0f / s;
        #pragma unroll
        for (int c = 0; c < 10; c++) out[row * 10 + c] = v[c] * inv;
    }
}

// ---------------------------------------------------------------------------
extern "C" void kernel_launch(void* const* d_in, const int* in_sizes, int n_in,
                              void* d_out, int out_size)
{
    const int*   src = (const int*)  d_in[0];
    const int*   dst = (const int*)  d_in[1];
    const float* W1  = (const float*)d_in[2];
    const float* b1  = (const float*)d_in[3];
    const float* W2  = (const float*)d_in[4];
    const float* b2  = (const float*)d_in[5];
    const float* Wa  = (const float*)d_in[6];
    const float* ba  = (const float*)d_in[7];
    const float* Wb  = (const float*)d_in[8];
    const float* bb  = (const float*)d_in[9];
    const float* Wc  = (const float*)d_in[10];
    const float* bc  = (const float*)d_in[11];
    const float* Wd  = (const float*)d_in[12];
    const float* bd  = (const float*)d_in[13];
    const float* We  = (const float*)d_in[14];
    const float* be  = (const float*)d_in[15];
    float* out = (float*)d_out;

    bf16 *hgh, *hgl, *x1h, *x1l, *x2h, *x2l, *x3h, *x3l;
    bf16 *wah, *wal, *wbh, *wbl, *wch, *wcl, *wdh, *wdl;
    float* part;
    cudaGetSymbolAddress((void**)&hgh, g_hgh); cudaGetSymbolAddress((void**)&hgl, g_hgl);
    cudaGetSymbolAddress((void**)&x1h, g_x1h); cudaGetSymbolAddress((void**)&x1l, g_x1l);
    cudaGetSymbolAddress((void**)&x2h, g_x2h); cudaGetSymbolAddress((void**)&x2l, g_x2l);
    cudaGetSymbolAddress((void**)&x3h, g_x3h); cudaGetSymbolAddress((void**)&x3l, g_x3l);
    cudaGetSymbolAddress((void**)&wah, g_wta_h); cudaGetSymbolAddress((void**)&wal, g_wta_l);
    cudaGetSymbolAddress((void**)&wbh, g_wtb_h); cudaGetSymbolAddress((void**)&wbl, g_wtb_l);
    cudaGetSymbolAddress((void**)&wch, g_wtc_h); cudaGetSymbolAddress((void**)&wcl, g_wtc_l);
    cudaGetSymbolAddress((void**)&wdh, g_wtd_h); cudaGetSymbolAddress((void**)&wdl, g_wtd_l);
    cudaGetSymbolAddress((void**)&part, g_part);

    // SMEM: Cu 21600 + th 56576 + Ast 21504 + scalars 3584 + pool/colp 2816
    //       + seg 224 = 106304 B  (2 CTAs/SM)
    const int SMEM = 106304;
    cudaFuncSetAttribute(prep_gnn, cudaFuncAttributeMaxDynamicSharedMemorySize, SMEM);

    prep_gnn<<<512, 512, SMEM>>>(src, dst, W1, b1, W2, b2, Wa, Wb, Wc, Wd, hgh, hgl);

    // layer a: K=128, single chunk, fused epilogue
    gemm_bf16<<<dim3(8, 16, 1), 256>>>(hgh, hgl, wah, wal, nullptr, ba,
                                       x1h, x1l, 128, 128, 512);
    // layer b: K=512, split 2 -> grid 512
    gemm_bf16<<<dim3(16, 16, 2), 256>>>(x1h, x1l, wbh, wbl, part, nullptr,
                                        nullptr, nullptr, 512, 256, 1024);
    combine_relu<<<1024, 256>>>(part, 2, 512 * 1024, bb, x2h, x2l, 1024, 512 * 1024);
    // layer c: K=1024, split 4 -> grid 1024
    gemm_bf16<<<dim3(16, 16, 4), 256>>>(x2h, x2l, wch, wcl, part, nullptr,
                                        nullptr, nullptr, 1024, 256, 1024);
    combine_relu<<<1024, 256>>>(part, 4, 512 * 1024, bc, x3h, x3l, 1024, 512 * 1024);
    // layer d: K=1024, split 4 -> grid 512, partials consumed by head
    gemm_bf16<<<dim3(8, 16, 4), 256>>>(x3h, x3l, wdh, wdl, part, nullptr,
                                       nullptr, nullptr, 1024, 256, 512);

    head_softmax<<<64, 256>>>(part, bd, We, be, out);
}